// round 14
// baseline (speedup 1.0000x reference)
#include <cuda_runtime.h>
#include <cuda.h>
#include <cuda_bf16.h>
#include <math.h>
#include <stdint.h>
#include <stddef.h>

// ---------------- problem constants ----------------
#define Nn    4096
#define Hh    8
#define D0c   256
#define C1c   448
#define C2c   384
#define C3c   256
#define Kk    4
#define Mm    500
#define Gg    2000
#define NEGs  0.2f
#define LNEPS 1e-5f
#define MAXD  3584
#define MAXE  40960

// cg2 GEMM tiling: pair BM=256 (128/CTA), BN=256 (B split 128/CTA), BK=64.
// Per-CTA stage: Ahi 16K + Alo 16K + Bhi(half) 16K + Blo(half) 16K = 64KB.
#define NSTAGE  3
#define STAGE_B 65536u
#define OFF_AHI 0u
#define OFF_ALO 16384u
#define OFF_BHI 32768u
#define OFF_BLO 49152u
#define GEMM_SMEM (3u*STAGE_B + 1024u)
#define GEMM_THREADS 512

// per-layer B-buffer offsets (elements) so wconv can run ahead on stream s2
#define OFFB1 0ull
#define OFFB2 1048576ull
#define OFFB3 12582912ull
#define OFFBH 18874368ull
#define BTOT  23068672ull

#if (defined(__CUDA_ARCH_FEAT_SM103_ALL)) || \
    (defined(__CUDA_ARCH_SPECIFIC__) && (__CUDA_ARCH_SPECIFIC__ == 1030))
#define HAS_TC 1
#else
#define HAS_TC 0
#endif

// ---------------- scratch (device globals) ----------------
__device__ float          g_xp[(size_t)Nn * MAXD];
__device__ __nv_bfloat16  g_ahi[(size_t)Nn * MAXD];
__device__ __nv_bfloat16  g_alo[(size_t)Nn * MAXD];
__device__ __nv_bfloat16  g_bhi[BTOT];
__device__ __nv_bfloat16  g_blo[BTOT];
__device__ float g_s[Kk * Nn * Hh];
__device__ float g_d[Kk * Nn * Hh];
__device__ int   g_deg[Nn];
__device__ int   g_off[Nn + 1];
__device__ int   g_cur[Nn];
__device__ int   g_csr[MAXE];

// ---------------- PTX helpers ----------------
__device__ __forceinline__ uint32_t smem_u32(const void* p) {
    uint32_t a;
    asm("{ .reg .u64 t; cvta.to.shared.u64 t, %1; cvt.u32.u64 %0, t; }"
        : "=r"(a) : "l"(p));
    return a;
}
__device__ __forceinline__ uint32_t clrank() {
    uint32_t r;
    asm("mov.u32 %0, %%cluster_ctarank;" : "=r"(r));
    return r;
}

#if HAS_TC
__device__ __forceinline__ uint32_t elect1() {
    uint32_t p;
    asm volatile("{ .reg .pred p; elect.sync _|p, 0xFFFFFFFF; selp.b32 %0,1,0,p; }"
                 : "=r"(p));
    return p;
}
#define MBARRIER_INIT(addr, cnt) \
    asm volatile("mbarrier.init.shared.b64 [%0], %1;" :: "r"(addr), "r"(cnt) : "memory")
#define MBARRIER_EXPECT_TX(addr, bytes) \
    asm volatile("mbarrier.arrive.expect_tx.shared.b64 _, [%0], %1;" \
                 :: "r"(addr), "r"(bytes) : "memory")

#define MBAR_WAIT(mbar, parity) do {                                          \
    uint32_t _m = (mbar), _p = (parity), _done;                               \
    asm volatile("{\n\t.reg .pred p;\n\t"                                     \
        "mbarrier.try_wait.parity.acquire.cta.shared::cta.b64 p, [%1], %2;\n\t"\
        "selp.b32 %0, 1, 0, p;\n\t}"                                          \
        : "=r"(_done) : "r"(_m), "r"(_p) : "memory");                          \
    if (!_done) {                                                             \
        asm volatile("{\n\t.reg .pred P1;\n\t"                                \
            "WL_%=:\n\t"                                                      \
            "mbarrier.try_wait.parity.acquire.cta.shared::cta.b64 P1, [%0], %1, 0x989680;\n\t" \
            "@P1 bra.uni WD_%=;\n\t"                                          \
            "bra.uni WL_%=;\n\t"                                              \
            "WD_%=:\n\t}"                                                     \
            :: "r"(_m), "r"(_p) : "memory");                                  \
    }                                                                         \
} while (0)

#define TMA_LD2D(dst, map, cx, cy, mb) \
    asm volatile("cp.async.bulk.tensor.2d.shared::cta.global.tile.mbarrier::complete_tx::bytes " \
                 "[%0], [%1, {%2, %3}], [%4];" \
                 :: "r"(dst), "l"(map), "r"(cx), "r"(cy), "r"(mb) : "memory")

#define TC_ALLOC_CG2(smaddr, ncols) \
    asm volatile("tcgen05.alloc.cta_group::2.sync.aligned.shared::cta.b32 [%0], %1;" \
                 :: "r"(smaddr), "r"(ncols) : "memory")
#define TC_DEALLOC_CG2(tm, ncols) \
    asm volatile("tcgen05.dealloc.cta_group::2.sync.aligned.b32 %0, %1;" :: "r"(tm), "r"(ncols))
#define TC_RELINQ_CG2() \
    asm volatile("tcgen05.relinquish_alloc_permit.cta_group::2.sync.aligned;")
#define TC_COMMIT_MC(mb) \
    asm volatile("tcgen05.commit.cta_group::2.mbarrier::arrive::one.shared::cluster.multicast::cluster.b64 [%0], %1;" \
                 :: "r"(mb), "h"((uint16_t)0x3) : "memory")
#define ARRIVE_PEER0(addr) \
    asm volatile("{ .reg .b32 r; mapa.shared::cluster.u32 r, %0, %1; " \
                 "mbarrier.arrive.shared::cluster.b64 _, [r]; }" \
                 :: "r"(addr), "r"(0u) : "memory")
#define CLUSTER_SYNC() do { \
    asm volatile("barrier.cluster.arrive.aligned;" ::: "memory"); \
    asm volatile("barrier.cluster.wait.aligned;" ::: "memory"); \
} while (0)
#define TC_FENCE_AFTER()  asm volatile("tcgen05.fence::after_thread_sync;" ::: "memory")
#define TC_FENCE_BEFORE() asm volatile("tcgen05.fence::before_thread_sync;" ::: "memory")
#define TC_WAIT_LD()      asm volatile("tcgen05.wait::ld.sync.aligned;" ::: "memory")

// cg2 bf16 SS MMA (8-element disable-lane vector)
__device__ __forceinline__ void mma_f16_ss_cg2(uint32_t d, uint64_t a, uint64_t b,
                                               uint32_t idesc, uint32_t en) {
    asm volatile("{\n\t.reg .pred p;\n\tsetp.ne.u32 p, %5, 0;\n\t"
        "tcgen05.mma.cta_group::2.kind::f16 [%0], %1, %2, %3, "
        "{%4,%4,%4,%4,%4,%4,%4,%4}, p;\n\t}"
        :: "r"(d), "l"(a), "l"(b), "r"(idesc), "r"(0u), "r"(en) : "memory");
}

#define TC_LD_X32(r, tm) \
    asm volatile("tcgen05.ld.sync.aligned.32x32b.x32.b32 " \
        "{%0, %1, %2, %3, %4, %5, %6, %7, " \
        " %8, %9, %10, %11, %12, %13, %14, %15, " \
        " %16, %17, %18, %19, %20, %21, %22, %23, " \
        " %24, %25, %26, %27, %28, %29, %30, %31}, [%32];" \
        : "=r"((r)[0]),  "=r"((r)[1]),  "=r"((r)[2]),  "=r"((r)[3]), \
          "=r"((r)[4]),  "=r"((r)[5]),  "=r"((r)[6]),  "=r"((r)[7]), \
          "=r"((r)[8]),  "=r"((r)[9]),  "=r"((r)[10]), "=r"((r)[11]), \
          "=r"((r)[12]), "=r"((r)[13]), "=r"((r)[14]), "=r"((r)[15]), \
          "=r"((r)[16]), "=r"((r)[17]), "=r"((r)[18]), "=r"((r)[19]), \
          "=r"((r)[20]), "=r"((r)[21]), "=r"((r)[22]), "=r"((r)[23]), \
          "=r"((r)[24]), "=r"((r)[25]), "=r"((r)[26]), "=r"((r)[27]), \
          "=r"((r)[28]), "=r"((r)[29]), "=r"((r)[30]), "=r"((r)[31]) \
        : "r"(tm))

#define SDESC_BASE ((2ull << 61) | (1ull << 46) | (64ull << 32) | (1ull << 16))
#define MKDESC(a) (SDESC_BASE | ((uint64_t)((a) >> 4) & 0x3FFFull))

// idesc cg2: f32 acc, bf16 A/B, M=256 (16<<24), N=256 (32<<17) — round-6 proven
#define IDESC_CG2 0x10400490u
#endif // HAS_TC

// ---------------- small utility kernels ----------------
__global__ void k_init_deg(int* deg) {
    int i = blockIdx.x * blockDim.x + threadIdx.x;
    if (i < Nn) deg[i] = 1;
}
__global__ void k_count(const int* __restrict__ ei, int E, int* deg) {
    int i = blockIdx.x * blockDim.x + threadIdx.x;
    if (i < E) atomicAdd(&deg[ei[E + i]], 1);
}
__global__ void k_zero_i(int* p, int n) {
    int i = blockIdx.x * blockDim.x + threadIdx.x;
    if (i < n) p[i] = 0;
}
__global__ void k_zero_f(float* p, size_t n) {
    size_t i = (size_t)blockIdx.x * blockDim.x + threadIdx.x;
    size_t stride = (size_t)gridDim.x * blockDim.x;
    for (; i < n; i += stride) p[i] = 0.f;
}
__global__ void k_scan(const int* __restrict__ deg, int* __restrict__ off) {
    __shared__ int warp_sums[32];
    int tid = threadIdx.x, lane = tid & 31, wid = tid >> 5;
    int base = tid * 4;
    int v0 = deg[base], v1 = deg[base + 1], v2 = deg[base + 2], v3 = deg[base + 3];
    int t = v0 + v1 + v2 + v3;
    int sc = t;
    #pragma unroll
    for (int o = 1; o < 32; o <<= 1) {
        int u = __shfl_up_sync(0xffffffffu, sc, o);
        if (lane >= o) sc += u;
    }
    if (lane == 31) warp_sums[wid] = sc;
    __syncthreads();
    if (wid == 0) {
        int ws = warp_sums[lane];
        #pragma unroll
        for (int o = 1; o < 32; o <<= 1) {
            int u = __shfl_up_sync(0xffffffffu, ws, o);
            if (lane >= o) ws += u;
        }
        warp_sums[lane] = ws;
    }
    __syncthreads();
    int prefix = sc - t + (wid > 0 ? warp_sums[wid - 1] : 0);
    off[base] = prefix; off[base + 1] = prefix + v0;
    off[base + 2] = prefix + v0 + v1; off[base + 3] = prefix + v0 + v1 + v2;
    if (tid == 1023) off[Nn] = prefix + t;
}
__global__ void k_scatter(const int* __restrict__ ei, int E, int Ein,
                          const int* __restrict__ off, int* __restrict__ cur,
                          int* __restrict__ csr) {
    int e = blockIdx.x * blockDim.x + threadIdx.x;
    if (e >= Ein) return;
    int s, d;
    if (e < E) { s = ei[e]; d = ei[E + e]; }
    else       { s = e - E; d = e - E; }
    int p = atomicAdd(&cur[d], 1);
    csr[off[d] + p] = s;
}

// ---------------- fp32 -> bf16 hi/lo (rows) ----------------
__global__ void k_conv_rows(const float* __restrict__ a, size_t n,
                            __nv_bfloat16* __restrict__ hi,
                            __nv_bfloat16* __restrict__ lo) {
    size_t i = (size_t)blockIdx.x * blockDim.x + threadIdx.x;
    size_t st = (size_t)gridDim.x * blockDim.x;
    for (; i < n; i += st) {
        float v = a[i];
        __nv_bfloat16 h = __float2bfloat16(v);
        hi[i] = h;
        lo[i] = __float2bfloat16(v - __bfloat162float(h));
    }
}

// ---------------- weight convert + transpose ----------------
__global__ void k_wconv_t(const float* __restrict__ W, int K, int N,
                          __nv_bfloat16* __restrict__ hi,
                          __nv_bfloat16* __restrict__ lo) {
    __shared__ float s[32][33];
    int n0 = blockIdx.x * 32, k0 = blockIdx.y * 32;
    int tx = threadIdx.x, ty = threadIdx.y;
    #pragma unroll
    for (int i = 0; i < 4; i++) {
        int k = k0 + ty + i * 8;
        int n = n0 + tx;
        float v = (n < N) ? W[(size_t)k * N + n] : 0.f;
        s[ty + i * 8][tx] = v;
    }
    __syncthreads();
    #pragma unroll
    for (int i = 0; i < 4; i++) {
        int n = n0 + ty + i * 8;
        float v = s[tx][ty + i * 8];
        __nv_bfloat16 h = __float2bfloat16(v);
        size_t o = (size_t)n * K + k0 + tx;
        hi[o] = h;
        lo[o] = __float2bfloat16(v - __bfloat162float(h));
    }
}

// ---------------- TMA-fed cg2 tcgen05 GEMM (3-stage, 512 threads) ------------
// C[Mr,Nd] = A * Bt^T, bf16 hi/lo split (3 MMA passes), fp32 TMEM acc.
// Cluster pair: CTA rank r loads A rows [by*256+128r,+128) and B rows
// [col0+128r,+128). rank0 issues cg2 M=256/N=256 MMAs; commit multicasts to
// both CTAs' empty barriers; rank1 signals stage-full via cluster arrive.
__global__ __launch_bounds__(GEMM_THREADS, 1) __cluster_dims__(2, 1, 1)
void k_tma_gemm(const __grid_constant__ CUtensorMap mAhi,
                const __grid_constant__ CUtensorMap mAlo,
                const __grid_constant__ CUtensorMap mBhi,
                const __grid_constant__ CUtensorMap mBlo,
                const __nv_bfloat16* __restrict__ Ahi,
                const __nv_bfloat16* __restrict__ Alo,
                const __nv_bfloat16* __restrict__ Bhi,
                const __nv_bfloat16* __restrict__ Blo,
                float* __restrict__ C, int Kd, int Nd) {
    extern __shared__ char smraw[];
#if HAS_TC
    __shared__ uint32_t sh_tmem;
    __shared__ uint64_t sh_bar[3 * NSTAGE];   // full[3] empty[3] peerf[3]

    int tid = threadIdx.x, wid = tid >> 5, lane = tid & 31;
    uint32_t raw = smem_u32(smraw);
    uint32_t pad = (1024u - (raw & 1023u)) & 1023u;
    uint32_t smbase = raw + pad;
    uint32_t rank = clrank();

    uint32_t fullb[NSTAGE], emptyb[NSTAGE], peerf[NSTAGE];
    #pragma unroll
    for (int s = 0; s < NSTAGE; s++) {
        fullb[s]  = smem_u32(&sh_bar[s]);
        emptyb[s] = smem_u32(&sh_bar[NSTAGE + s]);
        peerf[s]  = smem_u32(&sh_bar[2 * NSTAGE + s]);
    }
    if (tid == 0) {
        #pragma unroll
        for (int s = 0; s < NSTAGE; s++) {
            MBARRIER_INIT(fullb[s], 1);
            MBARRIER_INIT(emptyb[s], 1);
            MBARRIER_INIT(peerf[s], 1);
        }
    }
    if (wid == 0) { TC_ALLOC_CG2(smem_u32(&sh_tmem), 256); TC_RELINQ_CG2(); }
    __syncthreads();
    CLUSTER_SYNC();   // barriers + TMEM visible cluster-wide before arrivals
    uint32_t tmem = sh_tmem;

    int col0 = (blockIdx.x >> 1) * 256;
    int rowA = blockIdx.y * 256 + (int)rank * 128;   // this CTA's A rows
    int rowB = col0 + (int)rank * 128;               // this CTA's B half
    const int NC = Kd >> 6;

    if (wid == 0 && elect1()) {
        int npro = NC < NSTAGE ? NC : NSTAGE;
        for (int c = 0; c < npro; c++) {
            uint32_t st = smbase + (uint32_t)c * STAGE_B;
            MBARRIER_EXPECT_TX(fullb[c], STAGE_B);
            TMA_LD2D(st + OFF_AHI, &mAhi, c * 64, rowA, fullb[c]);
            TMA_LD2D(st + OFF_ALO, &mAlo, c * 64, rowA, fullb[c]);
            TMA_LD2D(st + OFF_BHI, &mBhi, c * 64, rowB, fullb[c]);
            TMA_LD2D(st + OFF_BLO, &mBlo, c * 64, rowB, fullb[c]);
        }
        int s = 0; uint32_t ph = 0;
        for (int c = 0; c < NC; c++) {
            MBAR_WAIT(fullb[s], ph);
            if (rank == 0) {
                MBAR_WAIT(peerf[s], ph);   // rank1's stage s ready
                uint32_t sb = smbase + (uint32_t)s * STAGE_B;
                uint64_t dAh = MKDESC(sb + OFF_AHI);
                uint64_t dAl = MKDESC(sb + OFF_ALO);
                uint64_t dBh = MKDESC(sb + OFF_BHI);
                uint64_t dBl = MKDESC(sb + OFF_BLO);
                #pragma unroll
                for (int ks = 0; ks < 4; ++ks) {
                    uint64_t ah = dAh + ks * 2;
                    uint64_t al = dAl + ks * 2;
                    uint64_t bh = dBh + ks * 2;
                    uint64_t bl = dBl + ks * 2;
                    uint32_t en = (c == 0 && ks == 0) ? 0u : 1u;
                    mma_f16_ss_cg2(tmem, ah, bh, IDESC_CG2, en);
                    mma_f16_ss_cg2(tmem, ah, bl, IDESC_CG2, 1u);
                    mma_f16_ss_cg2(tmem, al, bh, IDESC_CG2, 1u);
                }
                TC_COMMIT_MC(emptyb[s]);
            } else {
                ARRIVE_PEER0(peerf[s]);    // tell rank0 our stage s is full
            }
            if (c + NSTAGE < NC) {
                MBAR_WAIT(emptyb[s], ph);  // chunk c's MMAs done with stage s
                uint32_t sb = smbase + (uint32_t)s * STAGE_B;
                MBARRIER_EXPECT_TX(fullb[s], STAGE_B);
                int cx = (c + NSTAGE) * 64;
                TMA_LD2D(sb + OFF_AHI, &mAhi, cx, rowA, fullb[s]);
                TMA_LD2D(sb + OFF_ALO, &mAlo, cx, rowA, fullb[s]);
                TMA_LD2D(sb + OFF_BHI, &mBhi, cx, rowB, fullb[s]);
                TMA_LD2D(sb + OFF_BLO, &mBlo, cx, rowB, fullb[s]);
            }
            if (++s == NSTAGE) { s = 0; ph ^= 1; }
        }
        // final: last chunk's MMA completion (in-order consumer parity)
        int sl = (NC - 1) % NSTAGE;
        uint32_t pl = (uint32_t)((NC - 1) / NSTAGE) & 1u;
        MBAR_WAIT(emptyb[sl], pl);
    }

    __syncthreads();   // producer done => MMAs complete for this CTA's TMEM
    TC_FENCE_AFTER();

    // 16-warp epilogue: warp w -> subpartition (w&3) rows, 64-col block (w>>2)
    {
        int sub = wid & 3;
        int cb2 = wid >> 2;
        int r = rowA + sub * 32 + lane;
        float* crow = C + (size_t)r * Nd + col0 + cb2 * 64;
        #pragma unroll
        for (int half = 0; half < 2; ++half) {
            uint32_t dr[32];
            TC_LD_X32(dr, tmem + cb2 * 64 + half * 32);
            TC_WAIT_LD();
            #pragma unroll
            for (int q = 0; q < 8; ++q)
                *(uint4*)(crow + half * 32 + q * 4) = *(uint4*)&dr[q * 4];
        }
        TC_FENCE_BEFORE();
    }
    __syncthreads();
    if (wid == 0) TC_DEALLOC_CG2(tmem, 256);
    CLUSTER_SYNC();    // no CTA exits while peer may still touch shared state
#else
    // ---------- FFMA fallback (non-sm_103a compilation pass) ----------
    float* As = (float*)smraw;
    float* Bs = As + 16 * 128;
    int tid  = threadIdx.x;
    uint32_t rank = clrank();
    int row0 = blockIdx.y * 256 + (int)rank * 128;
    int col0 = (blockIdx.x >> 1) * 256;
    int tr = ((tid & 255) >> 4) << 3;
    int tc = (tid & 15) << 3;
    bool active = tid < 256;
    for (int half = 0; half < 2; ++half) {
        int colh = col0 + half * 128;
        float acc[8][8];
        #pragma unroll
        for (int i = 0; i < 8; i++)
            #pragma unroll
            for (int j = 0; j < 8; j++) acc[i][j] = 0.f;
        for (int k0 = 0; k0 < Kd; k0 += 16) {
            if (active) {
                int r = tid >> 1, kk0 = (tid & 1) * 8;
                const __nv_bfloat16* ah = Ahi + (size_t)(row0 + r) * Kd + k0 + kk0;
                const __nv_bfloat16* al = Alo + (size_t)(row0 + r) * Kd + k0 + kk0;
                #pragma unroll
                for (int j = 0; j < 8; j++)
                    As[(kk0 + j) * 128 + r] =
                        __bfloat162float(ah[j]) + __bfloat162float(al[j]);
                const __nv_bfloat16* bhp = Bhi + (size_t)(colh + r) * Kd + k0 + kk0;
                const __nv_bfloat16* blp = Blo + (size_t)(colh + r) * Kd + k0 + kk0;
                #pragma unroll
                for (int j = 0; j < 8; j++)
                    Bs[(kk0 + j) * 128 + r] =
                        __bfloat162float(bhp[j]) + __bfloat162float(blp[j]);
            }
            __syncthreads();
            if (active) {
                #pragma unroll
                for (int kk = 0; kk < 16; kk++) {
                    float av[8], bv[8];
                    #pragma unroll
                    for (int i = 0; i < 8; i++) av[i] = As[kk * 128 + tr + i];
                    #pragma unroll
                    for (int j = 0; j < 8; j++) bv[j] = Bs[kk * 128 + tc + j];
                    #pragma unroll
                    for (int i = 0; i < 8; i++)
                        #pragma unroll
                        for (int j = 0; j < 8; j++)
                            acc[i][j] = fmaf(av[i], bv[j], acc[i][j]);
                }
            }
            __syncthreads();
        }
        if (active) {
            #pragma unroll
            for (int i = 0; i < 8; i++) {
                float* cp = C + (size_t)(row0 + tr + i) * Nd + colh + tc;
                #pragma unroll
                for (int j = 0; j < 8; j++) cp[j] = acc[i][j];
            }
        }
        __syncthreads();
    }
#endif
}

// ---------------- attention coefficients (GAT layers) ----------------
__global__ void k_alpha(const float* __restrict__ xp, int ldx,
                        const float* __restrict__ as_, const float* __restrict__ ad_,
                        float* __restrict__ sv, float* __restrict__ dv, int C, int Hx) {
    int gw = (blockIdx.x * blockDim.x + threadIdx.x) >> 5;
    int lane = threadIdx.x & 31;
    if (gw >= Nn * Hx) return;
    int n = gw / Hx, h = gw % Hx;
    const float* row = xp + (size_t)n * ldx + (size_t)h * C;
    float ss = 0.f, dd = 0.f;
    for (int c = lane; c < C; c += 32) {
        float v = row[c];
        ss = fmaf(v, as_[h * C + c], ss);
        dd = fmaf(v, ad_[h * C + c], dd);
    }
    #pragma unroll
    for (int o = 16; o > 0; o >>= 1) {
        ss += __shfl_down_sync(0xffffffffu, ss, o);
        dd += __shfl_down_sync(0xffffffffu, dd, o);
    }
    if (lane == 0) { sv[n * Hx + h] = ss; dv[n * Hx + h] = dd; }
}

// ---------------- hydra merged alpha: grid.y = k ----------------
__global__ void k_alpha_h(const float* __restrict__ xp,
                          const float* __restrict__ ash, const float* __restrict__ adh,
                          float* __restrict__ sv, float* __restrict__ dv) {
    int k = blockIdx.y;
    int gw = (blockIdx.x * blockDim.x + threadIdx.x) >> 5;
    int lane = threadIdx.x & 31;
    if (gw >= Nn) return;
    const float* row = xp + (size_t)gw * (Kk * 512) + k * 512;
    const float* a_s = ash + k * Mm;
    const float* a_d = adh + k * Mm;
    float ss = 0.f, dd = 0.f;
    for (int c = lane; c < Mm; c += 32) {
        float v = row[c];
        ss = fmaf(v, a_s[c], ss);
        dd = fmaf(v, a_d[c], dd);
    }
    #pragma unroll
    for (int o = 16; o > 0; o >>= 1) {
        ss += __shfl_down_sync(0xffffffffu, ss, o);
        dd += __shfl_down_sync(0xffffffffu, dd, o);
    }
    if (lane == 0) { sv[k * Nn + gw] = ss; dv[k * Nn + gw] = dd; }
}

// ---------------- GAT aggregate + fused softmax + bias + ReLU + LN ----------
#define EB 512
__global__ __launch_bounds__(256) void k_agg_post(const float* __restrict__ xp,
        const float* __restrict__ sv, const float* __restrict__ dv,
        const int* __restrict__ off, const int* __restrict__ csr,
        const float* __restrict__ bias, const float* __restrict__ gamma,
        const float* __restrict__ beta,
        __nv_bfloat16* __restrict__ ohi, __nv_bfloat16* __restrict__ olo, int C) {
    int n = blockIdx.x;
    int beg = off[n], end = off[n + 1];
    int cnt = end - beg;
    int D = Hh * C;
    __shared__ float sha[EB * Hh];
    __shared__ int   ssrc[EB];
    __shared__ float red[256];
    int tid = threadIdx.x, wid = tid >> 5, lane = tid & 31;

    for (int i = tid; i < cnt; i += 256) ssrc[i] = csr[beg + i];
    __syncthreads();

    {   // warp `wid` computes softmax for head `wid`
        int h = wid;
        float dh = dv[n * Hh + h];
        float mm = -1e30f;
        for (int e = lane; e < cnt; e += 32) {
            float v = sv[ssrc[e] * Hh + h] + dh;
            v = v > 0.f ? v : NEGs * v;
            mm = fmaxf(mm, v);
        }
        #pragma unroll
        for (int o = 16; o > 0; o >>= 1)
            mm = fmaxf(mm, __shfl_xor_sync(0xffffffffu, mm, o));
        float z = 0.f;
        for (int e = lane; e < cnt; e += 32) {
            float v = sv[ssrc[e] * Hh + h] + dh;
            v = v > 0.f ? v : NEGs * v;
            z += expf(v - mm);
        }
        #pragma unroll
        for (int o = 16; o > 0; o >>= 1)
            z += __shfl_xor_sync(0xffffffffu, z, o);
        float inv = 1.f / (z + 1e-16f);
        for (int e = lane; e < cnt; e += 32) {
            float v = sv[ssrc[e] * Hh + h] + dh;
            v = v > 0.f ? v : NEGs * v;
            sha[e * Hh + h] = expf(v - mm) * inv;
        }
    }
    __syncthreads();

    float4 acc4[4];
    int    hj4[4];
    #pragma unroll
    for (int i = 0; i < 4; i++) {
        int j = (i << 10) + (tid << 2);
        hj4[i] = (j < D) ? (j / C) : 0;
        acc4[i] = make_float4(0.f, 0.f, 0.f, 0.f);
    }

    for (int e = 0; e < cnt; e++) {
        int sn = ssrc[e];
        const float4* xr = (const float4*)(xp + (size_t)sn * D);
        const float*  al = &sha[e * Hh];
        #pragma unroll
        for (int i = 0; i < 4; i++) {
            int j = (i << 10) + (tid << 2);
            if (j < D) {
                float a = al[hj4[i]];
                float4 v = xr[(i << 8) + tid];
                acc4[i].x = fmaf(a, v.x, acc4[i].x);
                acc4[i].y = fmaf(a, v.y, acc4[i].y);
                acc4[i].z = fmaf(a, v.z, acc4[i].z);
                acc4[i].w = fmaf(a, v.w, acc4[i].w);
            }
        }
    }

    const float4* b4 = (const float4*)bias;
    float lsum = 0.f;
    #pragma unroll
    for (int i = 0; i < 4; i++) {
        int j = (i << 10) + (tid << 2);
        if (j < D) {
            float4 bb = b4[(i << 8) + tid];
            acc4[i].x = fmaxf(acc4[i].x + bb.x, 0.f);
            acc4[i].y = fmaxf(acc4[i].y + bb.y, 0.f);
            acc4[i].z = fmaxf(acc4[i].z + bb.z, 0.f);
            acc4[i].w = fmaxf(acc4[i].w + bb.w, 0.f);
            lsum += acc4[i].x + acc4[i].y + acc4[i].z + acc4[i].w;
        }
    }
    red[tid] = lsum; __syncthreads();
    for (int s2 = 128; s2 > 0; s2 >>= 1) {
        if (tid < s2) red[tid] += red[tid + s2];
        __syncthreads();
    }
    float mean = red[0] / (float)D;
    __syncthreads();
    float lsq = 0.f;
    #pragma unroll
    for (int i = 0; i < 4; i++) {
        int j = (i << 10) + (tid << 2);
        if (j < D) {
            float a = acc4[i].x - mean, b = acc4[i].y - mean;
            float c = acc4[i].z - mean, d = acc4[i].w - mean;
            lsq = fmaf(a, a, lsq); lsq = fmaf(b, b, lsq);
            lsq = fmaf(c, c, lsq); lsq = fmaf(d, d, lsq);
        }
    }
    red[tid] = lsq; __syncthreads();
    for (int s2 = 128; s2 > 0; s2 >>= 1) {
        if (tid < s2) red[tid] += red[tid + s2];
        __syncthreads();
    }
    float rstd = rsqrtf(red[0] / (float)D + LNEPS);
    const float4* g4  = (const float4*)gamma;
    const float4* be4 = (const float4*)beta;
    size_t rowoff = (size_t)n * D;
    #pragma unroll
    for (int i = 0; i < 4; i++) {
        int j = (i << 10) + (tid << 2);
        if (j < D) {
            float4 gg = g4[(i << 8) + tid];
            float4 be = be4[(i << 8) + tid];
            float vv[4] = {
                (acc4[i].x - mean) * rstd * gg.x + be.x,
                (acc4[i].y - mean) * rstd * gg.y + be.y,
                (acc4[i].z - mean) * rstd * gg.z + be.z,
                (acc4[i].w - mean) * rstd * gg.w + be.w
            };
            #pragma unroll
            for (int q = 0; q < 4; q++) {
                __nv_bfloat16 h = __float2bfloat16(vv[q]);
                ohi[rowoff + j + q] = h;
                olo[rowoff + j + q] = __float2bfloat16(vv[q] - __bfloat162float(h));
            }
        }
    }
}

// ---------------- hydra aggregate merged, fused softmax: grid = (Nn, Kk) -----
__global__ __launch_bounds__(256) void k_agg_hydra(const float* __restrict__ xp,
        const float* __restrict__ sv, const float* __restrict__ dv,
        const int* __restrict__ off, const int* __restrict__ csr,
        const float* __restrict__ bh, const int* __restrict__ idx,
        float* __restrict__ full, float* __restrict__ ph) {
    int n = blockIdx.x, k = blockIdx.y;
    int beg = off[n], end = off[n + 1];
    int cnt = end - beg;
    __shared__ float sha[EB];
    __shared__ int   ssrc[EB];
    int tid = threadIdx.x, wid = tid >> 5, lane = tid & 31;

    for (int i = tid; i < cnt; i += 256) ssrc[i] = csr[beg + i];
    __syncthreads();

    if (wid == 0) {
        const float* svk = sv + (size_t)k * Nn;
        float dh = dv[(size_t)k * Nn + n];
        float mm = -1e30f;
        for (int e = lane; e < cnt; e += 32) {
            float v = svk[ssrc[e]] + dh;
            v = v > 0.f ? v : NEGs * v;
            mm = fmaxf(mm, v);
        }
        #pragma unroll
        for (int o = 16; o > 0; o >>= 1)
            mm = fmaxf(mm, __shfl_xor_sync(0xffffffffu, mm, o));
        float z = 0.f;
        for (int e = lane; e < cnt; e += 32) {
            float v = svk[ssrc[e]] + dh;
            v = v > 0.f ? v : NEGs * v;
            z += expf(v - mm);
        }
        #pragma unroll
        for (int o = 16; o > 0; o >>= 1)
            z += __shfl_xor_sync(0xffffffffu, z, o);
        float inv = 1.f / (z + 1e-16f);
        for (int e = lane; e < cnt; e += 32) {
            float v = svk[ssrc[e]] + dh;
            v = v > 0.f ? v : NEGs * v;
            sha[e] = expf(v - mm) * inv;
        }
    }
    __syncthreads();

    const float* xpk = xp + k * 512;
    const float* bias = bh + k * Mm;
    const int*  idxk = idx + k * Mm;
    float* phk = ph + (size_t)k * Nn * Mm;
    bool act = tid < 250;
    float2 acc = make_float2(0.f, 0.f);
    for (int e = 0; e < cnt; e++) {
        float a = sha[e];
        if (act) {
            const float2* xr = (const float2*)(xpk + (size_t)ssrc[e] * (Kk * 512));
            float2 v = xr[tid];
            acc.x = fmaf(a, v.x, acc.x);
            acc.y = fmaf(a, v.y, acc.y);
        }
    }
    if (act) {
        int j0 = tid * 2, j1 = j0 + 1;
        float v0 = acc.x + bias[j0];
        float v1 = acc.y + bias[j1];
        phk[(size_t)n * Mm + j0] = v0;
        phk[(size_t)n * Mm + j1] = v1;
        full[(size_t)n * Gg + idxk[j0]] = v0;
        full[(size_t)n * Gg + idxk[j1]] = v1;
    }
}

// ---------------- host: tensor-map encode via driver entry point --------------
typedef CUresult (*EncTiledFn)(CUtensorMap*, CUtensorMapDataType, cuuint32_t, void*,
                               const cuuint64_t*, const cuuint64_t*,
                               const cuuint32_t*, const cuuint32_t*,
                               CUtensorMapInterleave, CUtensorMapSwizzle,
                               CUtensorMapL2promotion, CUtensorMapFloatOOBfill);

static EncTiledFn get_enc() {
    static EncTiledFn fn = nullptr;
    if (!fn) {
        void* p = nullptr;
        cudaDriverEntryPointQueryResult st;
        cudaGetDriverEntryPoint("cuTensorMapEncodeTiled", &p, cudaEnableDefault, &st);
        fn = (EncTiledFn)p;
    }
    return fn;
}

static void enc_map(CUtensorMap* m, void* ptr, uint64_t kd, uint64_t rows) {
    cuuint64_t dims[2]    = { (cuuint64_t)kd, (cuuint64_t)rows };
    cuuint64_t strides[1] = { (cuuint64_t)(kd * 2) };
    cuuint32_t box[2]     = { 64u, 128u };
    cuuint32_t es[2]      = { 1u, 1u };
    get_enc()(m, CU_TENSOR_MAP_DATA_TYPE_BFLOAT16, 2, ptr, dims, strides, box, es,
              CU_TENSOR_MAP_INTERLEAVE_NONE, CU_TENSOR_MAP_SWIZZLE_128B,
              CU_TENSOR_MAP_L2_PROMOTION_L2_128B, CU_TENSOR_MAP_FLOAT_OOB_FILL_NONE);
}

// ---------------- host launch ----------------
extern "C" void kernel_launch(void* const* d_in, const int* in_sizes, int n_in,
                              void* d_out, int out_size) {
    const float* x   = (const float*)d_in[0];
    const int*   ei  = (const int*)  d_in[1];
    const float* W1  = (const float*)d_in[2];
    const float* as1 = (const float*)d_in[3];
    const float* ad1 = (const float*)d_in[4];
    const float* b1  = (const float*)d_in[5];
    const float* g1  = (const float*)d_in[6];
    const float* be1 = (const float*)d_in[7];
    const float* W2  = (const float*)d_in[8];
    const float* as2 = (const float*)d_in[9];
    const float* ad2 = (const float*)d_in[10];
    const float* b2  = (const float*)d_in[11];
    const float* g2  = (const float*)d_in[12];
    const float* be2 = (const float*)d_in[13];
    const float* W3  = (const float*)d_in[14];
    const float* as3 = (const float*)d_in[15];
    const float* ad3 = (const float*)d_in[16];
    const float* b3  = (const float*)d_in[17];
    const float* g3  = (const float*)d_in[18];
    const float* be3 = (const float*)d_in[19];
    const float* Wh  = (const float*)d_in[20];
    const float* ash = (const float*)d_in[21];
    const float* adh = (const float*)d_in[22];
    const float* bh  = (const float*)d_in[23];
    const int*   idx = (const int*)  d_in[24];

    int E = in_sizes[1] / 2;
    int Ein = E + Nn;

    void* p;
    cudaGetSymbolAddress(&p, g_xp);  float* d_xp = (float*)p;
    cudaGetSymbolAddress(&p, g_ahi); __nv_bfloat16* d_ahi = (__nv_bfloat16*)p;
    cudaGetSymbolAddress(&p, g_alo); __nv_bfloat16* d_alo = (__nv_bfloat16*)p;
    cudaGetSymbolAddress(&p, g_bhi); __nv_bfloat16* d_bhi = (__nv_bfloat16*)p;
    cudaGetSymbolAddress(&p, g_blo); __nv_bfloat16* d_blo = (__nv_bfloat16*)p;
    cudaGetSymbolAddress(&p, g_s);   float* d_s = (float*)p;
    cudaGetSymbolAddress(&p, g_d);   float* d_d = (float*)p;
    cudaGetSymbolAddress(&p, g_deg); int* d_deg = (int*)p;
    cudaGetSymbolAddress(&p, g_off); int* d_off = (int*)p;
    cudaGetSymbolAddress(&p, g_cur); int* d_cur = (int*)p;
    cudaGetSymbolAddress(&p, g_csr); int* d_csr = (int*)p;

    cudaFuncSetAttribute(k_tma_gemm, cudaFuncAttributeMaxDynamicSharedMemorySize,
                         GEMM_SMEM);

    static cudaStream_t s2 = nullptr;
    static cudaEvent_t evFork, evB[5];
    if (!s2) {
        cudaStreamCreateWithFlags(&s2, cudaStreamNonBlocking);
        cudaEventCreateWithFlags(&evFork, cudaEventDisableTiming);
        for (int i = 0; i < 5; i++)
            cudaEventCreateWithFlags(&evB[i], cudaEventDisableTiming);
    }

    const int D1 = Hh * C1c, D2 = Hh * C2c, D3 = Hh * C3c;
    const int NP = 512;
    dim3 tb(32, 8);
    CUtensorMap mAh, mAl, mBh, mBl;

    __nv_bfloat16* B1h = d_bhi + OFFB1; __nv_bfloat16* B1l = d_blo + OFFB1;
    __nv_bfloat16* B2h = d_bhi + OFFB2; __nv_bfloat16* B2l = d_blo + OFFB2;
    __nv_bfloat16* B3h = d_bhi + OFFB3; __nv_bfloat16* B3l = d_blo + OFFB3;
    __nv_bfloat16* BHh = d_bhi + OFFBH; __nv_bfloat16* BHl = d_blo + OFFBH;

    float* full = (float*)d_out;
    float* pho  = full + (size_t)Nn * Gg;

    cudaEventRecord(evFork, 0);
    cudaStreamWaitEvent(s2, evFork, 0);

    k_wconv_t<<<dim3(D1 / 32, D0c / 32), tb, 0, s2>>>(W1, D0c, D1, B1h, B1l);
    cudaEventRecord(evB[0], s2);

    k_conv_rows<<<1024, 256>>>(x, (size_t)Nn * D0c, d_ahi, d_alo);
    k_init_deg<<<Nn / 256, 256>>>(d_deg);

    enc_map(&mAh, d_ahi, D0c, Nn);
    enc_map(&mAl, d_alo, D0c, Nn);
    enc_map(&mBh, B1h, D0c, D1);
    enc_map(&mBl, B1l, D0c, D1);
    cudaStreamWaitEvent(0, evB[0], 0);
    k_tma_gemm<<<dim3(2 * (D1 / 256), Nn / 256), GEMM_THREADS, GEMM_SMEM>>>(
        mAh, mAl, mBh, mBl, d_ahi, d_alo, B1h, B1l, d_xp, D0c, D1);

    k_wconv_t<<<dim3(D2 / 32, D1 / 32), tb, 0, s2>>>(W2, D1, D2, B2h, B2l);
    cudaEventRecord(evB[1], s2);
    k_wconv_t<<<dim3(D3 / 32, D2 / 32), tb, 0, s2>>>(W3, D2, D3, B3h, B3l);
    cudaEventRecord(evB[2], s2);
    for (int k = 0; k < Kk; k++)
        k_wconv_t<<<dim3(NP / 32, D3 / 32), tb, 0, s2>>>(
            Wh + (size_t)k * D3 * Mm, D3, Mm,
            BHh + (size_t)k * NP * D3, BHl + (size_t)k * NP * D3);
    cudaEventRecord(evB[3], s2);
    k_zero_f<<<2048, 256, 0, s2>>>(full, (size_t)Nn * Gg);
    cudaEventRecord(evB[4], s2);

    k_count<<<(E + 255) / 256, 256>>>(ei, E, d_deg);
    k_scan<<<1, 1024>>>(d_deg, d_off);
    k_zero_i<<<Nn / 256, 256>>>(d_cur, Nn);
    k_scatter<<<(Ein + 255) / 256, 256>>>(ei, E, Ein, d_off, d_cur, d_csr);

    k_alpha<<<(Nn * Hh * 32) / 256, 256>>>(d_xp, D1, as1, ad1, d_s, d_d, C1c, Hh);
    k_agg_post<<<Nn, 256>>>(d_xp, d_s, d_d, d_off, d_csr, b1, g1, be1, d_ahi, d_alo, C1c);

    enc_map(&mAh, d_ahi, D1, Nn);
    enc_map(&mAl, d_alo, D1, Nn);
    enc_map(&mBh, B2h, D1, D2);
    enc_map(&mBl, B2l, D1, D2);
    cudaStreamWaitEvent(0, evB[1], 0);
    k_tma_gemm<<<dim3(2 * (D2 / 256), Nn / 256), GEMM_THREADS, GEMM_SMEM>>>(
        mAh, mAl, mBh, mBl, d_ahi, d_alo, B2h, B2l, d_xp, D1, D2);
    k_alpha<<<(Nn * Hh * 32) / 256, 256>>>(d_xp, D2, as2, ad2, d_s, d_d, C2c, Hh);
    k_agg_post<<<Nn, 256>>>(d_xp, d_s, d_d, d_off, d_csr, b2, g2, be2, d_ahi, d_alo, C2c);

    enc_map(&mAh, d_ahi, D2, Nn);
    enc_map(&mAl, d_alo, D2, Nn);
    enc_map(&mBh, B3h, D2, D3);
    enc_map(&mBl, B3l, D2, D3);
    cudaStreamWaitEvent(0, evB[2], 0);
    k_tma_gemm<<<dim3(2 * (D3 / 256), Nn / 256), GEMM_THREADS, GEMM_SMEM>>>(
        mAh, mAl, mBh, mBl, d_ahi, d_alo, B3h, B3l, d_xp, D2, D3);
    k_alpha<<<(Nn * Hh * 32) / 256, 256>>>(d_xp, D3, as3, ad3, d_s, d_d, C3c, Hh);
    k_agg_post<<<Nn, 256>>>(d_xp, d_s, d_d, d_off, d_csr, b3, g3, be3, d_ahi, d_alo, C3c);

    enc_map(&mAh, d_ahi, D3, Nn);
    enc_map(&mAl, d_alo, D3, Nn);
    enc_map(&mBh, BHh, D3, Kk * NP);
    enc_map(&mBl, BHl, D3, Kk * NP);
    cudaStreamWaitEvent(0, evB[3], 0);
    k_tma_gemm<<<dim3(2 * ((Kk * NP) / 256), Nn / 256), GEMM_THREADS, GEMM_SMEM>>>(
        mAh, mAl, mBh, mBl, d_ahi, d_alo, BHh, BHl, d_xp, D3, Kk * NP);

    k_alpha_h<<<dim3((Nn * 32) / 256, Kk), 256>>>(d_xp, ash, adh, d_s, d_d);
    cudaStreamWaitEvent(0, evB[4], 0);
    k_agg_hydra<<<dim3(Nn, Kk), 256>>>(d_xp, d_s, d_d, d_off, d_csr, bh, idx,
                                       full, pho);
}

// round 15
// speedup vs baseline: 1.0969x; 1.0969x over previous
#include <cuda_runtime.h>
#include <cuda.h>
#include <cuda_bf16.h>
#include <math.h>
#include <stdint.h>
#include <stddef.h>

// ---------------- problem constants ----------------
#define Nn    4096
#define Hh    8
#define D0c   256
#define C1c   448
#define C2c   384
#define C3c   256
#define Kk    4
#define Mm    500
#define Gg    2000
#define NEGs  0.2f
#define LNEPS 1e-5f
#define MAXD  3584
#define MAXE  40960

// GEMM tiling: BM=128, BN=256, BK=64 per chunk (cg1, bf16 hi/lo 3-pass)
#define STAGE_BYTES 98304u
#define OFF_AHI 0u
#define OFF_ALO 16384u
#define OFF_BHI 32768u
#define OFF_BLO 65536u
#define GEMM_SMEM (2u*STAGE_BYTES + 1024u)
#define GEMM_THREADS 512

// per-layer B-buffer offsets (elements) so wconv can run ahead on stream s2
#define OFFB1 0ull
#define OFFB2 1048576ull
#define OFFB3 12582912ull
#define OFFBH 18874368ull
#define BTOT  23068672ull

#if (defined(__CUDA_ARCH_FEAT_SM103_ALL)) || \
    (defined(__CUDA_ARCH_SPECIFIC__) && (__CUDA_ARCH_SPECIFIC__ == 1030))
#define HAS_TC 1
#else
#define HAS_TC 0
#endif

// ---------------- scratch (device globals) ----------------
__device__ float          g_xp[(size_t)Nn * MAXD];
__device__ __nv_bfloat16  g_ahi[(size_t)Nn * MAXD];
__device__ __nv_bfloat16  g_alo[(size_t)Nn * MAXD];
__device__ __nv_bfloat16  g_bhi[BTOT];
__device__ __nv_bfloat16  g_blo[BTOT];
__device__ float g_s[Kk * Nn * Hh];
__device__ float g_d[Kk * Nn * Hh];
__device__ int   g_deg[Nn];
__device__ int   g_off[Nn + 1];
__device__ int   g_cur[Nn];
__device__ int   g_csr[MAXE];

// ---------------- PTX helpers ----------------
__device__ __forceinline__ uint32_t smem_u32(const void* p) {
    uint32_t a;
    asm("{ .reg .u64 t; cvta.to.shared.u64 t, %1; cvt.u32.u64 %0, t; }"
        : "=r"(a) : "l"(p));
    return a;
}

#if HAS_TC
__device__ __forceinline__ uint32_t elect1() {
    uint32_t p;
    asm volatile("{ .reg .pred p; elect.sync _|p, 0xFFFFFFFF; selp.b32 %0,1,0,p; }"
                 : "=r"(p));
    return p;
}
#define MBARRIER_INIT(addr, cnt) \
    asm volatile("mbarrier.init.shared.b64 [%0], %1;" :: "r"(addr), "r"(cnt) : "memory")
#define MBARRIER_EXPECT_TX(addr, bytes) \
    asm volatile("mbarrier.arrive.expect_tx.shared.b64 _, [%0], %1;" \
                 :: "r"(addr), "r"(bytes) : "memory")

#define MBAR_WAIT(mbar, parity) do {                                          \
    uint32_t _m = (mbar), _p = (parity), _done;                               \
    asm volatile("{\n\t.reg .pred p;\n\t"                                     \
        "mbarrier.try_wait.parity.acquire.cta.shared::cta.b64 p, [%1], %2;\n\t"\
        "selp.b32 %0, 1, 0, p;\n\t}"                                          \
        : "=r"(_done) : "r"(_m), "r"(_p) : "memory");                          \
    if (!_done) {                                                             \
        asm volatile("{\n\t.reg .pred P1;\n\t"                                \
            "WL_%=:\n\t"                                                      \
            "mbarrier.try_wait.parity.acquire.cta.shared::cta.b64 P1, [%0], %1, 0x989680;\n\t" \
            "@P1 bra.uni WD_%=;\n\t"                                          \
            "bra.uni WL_%=;\n\t"                                              \
            "WD_%=:\n\t}"                                                     \
            :: "r"(_m), "r"(_p) : "memory");                                  \
    }                                                                         \
} while (0)

#define TMA_LD2D(dst, map, cx, cy, mb) \
    asm volatile("cp.async.bulk.tensor.2d.shared::cta.global.tile.mbarrier::complete_tx::bytes " \
                 "[%0], [%1, {%2, %3}], [%4];" \
                 :: "r"(dst), "l"(map), "r"(cx), "r"(cy), "r"(mb) : "memory")

#define TC_ALLOC(smaddr, ncols) \
    asm volatile("tcgen05.alloc.cta_group::1.sync.aligned.shared::cta.b32 [%0], %1;" \
                 :: "r"(smaddr), "r"(ncols) : "memory")
#define TC_DEALLOC(tm, ncols) \
    asm volatile("tcgen05.dealloc.cta_group::1.sync.aligned.b32 %0, %1;" :: "r"(tm), "r"(ncols))
#define TC_RELINQ() \
    asm volatile("tcgen05.relinquish_alloc_permit.cta_group::1.sync.aligned;")
#define TC_COMMIT(mb) \
    asm volatile("tcgen05.commit.cta_group::1.mbarrier::arrive::one.shared::cluster.b64 [%0];" \
                 :: "r"(mb) : "memory")
#define TC_FENCE_AFTER()  asm volatile("tcgen05.fence::after_thread_sync;" ::: "memory")
#define TC_FENCE_BEFORE() asm volatile("tcgen05.fence::before_thread_sync;" ::: "memory")
#define TC_WAIT_LD()      asm volatile("tcgen05.wait::ld.sync.aligned;" ::: "memory")

__device__ __forceinline__ void mma_f16_ss(uint32_t d, uint64_t a, uint64_t b,
                                           uint32_t idesc, uint32_t en) {
    asm volatile("{\n\t.reg .pred p;\n\tsetp.ne.u32 p, %5, 0;\n\t"
        "tcgen05.mma.cta_group::1.kind::f16 [%0], %1, %2, %3, {%4,%4,%4,%4}, p;\n\t}"
        :: "r"(d), "l"(a), "l"(b), "r"(idesc), "r"(0u), "r"(en) : "memory");
}

#define TC_LD_X32(r, tm) \
    asm volatile("tcgen05.ld.sync.aligned.32x32b.x32.b32 " \
        "{%0, %1, %2, %3, %4, %5, %6, %7, " \
        " %8, %9, %10, %11, %12, %13, %14, %15, " \
        " %16, %17, %18, %19, %20, %21, %22, %23, " \
        " %24, %25, %26, %27, %28, %29, %30, %31}, [%32];" \
        : "=r"((r)[0]),  "=r"((r)[1]),  "=r"((r)[2]),  "=r"((r)[3]), \
          "=r"((r)[4]),  "=r"((r)[5]),  "=r"((r)[6]),  "=r"((r)[7]), \
          "=r"((r)[8]),  "=r"((r)[9]),  "=r"((r)[10]), "=r"((r)[11]), \
          "=r"((r)[12]), "=r"((r)[13]), "=r"((r)[14]), "=r"((r)[15]), \
          "=r"((r)[16]), "=r"((r)[17]), "=r"((r)[18]), "=r"((r)[19]), \
          "=r"((r)[20]), "=r"((r)[21]), "=r"((r)[22]), "=r"((r)[23]), \
          "=r"((r)[24]), "=r"((r)[25]), "=r"((r)[26]), "=r"((r)[27]), \
          "=r"((r)[28]), "=r"((r)[29]), "=r"((r)[30]), "=r"((r)[31]) \
        : "r"(tm))

#define SDESC_BASE ((2ull << 61) | (1ull << 46) | (64ull << 32) | (1ull << 16))
#define MKDESC(a) (SDESC_BASE | ((uint64_t)((a) >> 4) & 0x3FFFull))

#define IDESC_128 0x08200490u
#endif // HAS_TC

// ---------------- small utility kernels ----------------
__global__ void k_init_deg(int* deg) {
    int i = blockIdx.x * blockDim.x + threadIdx.x;
    if (i < Nn) deg[i] = 1;
}
__global__ void k_count(const int* __restrict__ ei, int E, int* deg) {
    int i = blockIdx.x * blockDim.x + threadIdx.x;
    if (i < E) atomicAdd(&deg[ei[E + i]], 1);
}
__global__ void k_zero_i(int* p, int n) {
    int i = blockIdx.x * blockDim.x + threadIdx.x;
    if (i < n) p[i] = 0;
}
__global__ void k_zero_f(float* p, size_t n) {
    size_t i = (size_t)blockIdx.x * blockDim.x + threadIdx.x;
    size_t stride = (size_t)gridDim.x * blockDim.x;
    for (; i < n; i += stride) p[i] = 0.f;
}
__global__ void k_scan(const int* __restrict__ deg, int* __restrict__ off) {
    __shared__ int warp_sums[32];
    int tid = threadIdx.x, lane = tid & 31, wid = tid >> 5;
    int base = tid * 4;
    int v0 = deg[base], v1 = deg[base + 1], v2 = deg[base + 2], v3 = deg[base + 3];
    int t = v0 + v1 + v2 + v3;
    int sc = t;
    #pragma unroll
    for (int o = 1; o < 32; o <<= 1) {
        int u = __shfl_up_sync(0xffffffffu, sc, o);
        if (lane >= o) sc += u;
    }
    if (lane == 31) warp_sums[wid] = sc;
    __syncthreads();
    if (wid == 0) {
        int ws = warp_sums[lane];
        #pragma unroll
        for (int o = 1; o < 32; o <<= 1) {
            int u = __shfl_up_sync(0xffffffffu, ws, o);
            if (lane >= o) ws += u;
        }
        warp_sums[lane] = ws;
    }
    __syncthreads();
    int prefix = sc - t + (wid > 0 ? warp_sums[wid - 1] : 0);
    off[base] = prefix; off[base + 1] = prefix + v0;
    off[base + 2] = prefix + v0 + v1; off[base + 3] = prefix + v0 + v1 + v2;
    if (tid == 1023) off[Nn] = prefix + t;
}
__global__ void k_scatter(const int* __restrict__ ei, int E, int Ein,
                          const int* __restrict__ off, int* __restrict__ cur,
                          int* __restrict__ csr) {
    int e = blockIdx.x * blockDim.x + threadIdx.x;
    if (e >= Ein) return;
    int s, d;
    if (e < E) { s = ei[e]; d = ei[E + e]; }
    else       { s = e - E; d = e - E; }
    int p = atomicAdd(&cur[d], 1);
    csr[off[d] + p] = s;
}

// ---------------- fp32 -> bf16 hi/lo (rows) ----------------
__global__ void k_conv_rows(const float* __restrict__ a, size_t n,
                            __nv_bfloat16* __restrict__ hi,
                            __nv_bfloat16* __restrict__ lo) {
    size_t i = (size_t)blockIdx.x * blockDim.x + threadIdx.x;
    size_t st = (size_t)gridDim.x * blockDim.x;
    for (; i < n; i += st) {
        float v = a[i];
        __nv_bfloat16 h = __float2bfloat16(v);
        hi[i] = h;
        lo[i] = __float2bfloat16(v - __bfloat162float(h));
    }
}

// ---------------- weight convert + transpose ----------------
__global__ void k_wconv_t(const float* __restrict__ W, int K, int N,
                          __nv_bfloat16* __restrict__ hi,
                          __nv_bfloat16* __restrict__ lo) {
    __shared__ float s[32][33];
    int n0 = blockIdx.x * 32, k0 = blockIdx.y * 32;
    int tx = threadIdx.x, ty = threadIdx.y;
    #pragma unroll
    for (int i = 0; i < 4; i++) {
        int k = k0 + ty + i * 8;
        int n = n0 + tx;
        float v = (n < N) ? W[(size_t)k * N + n] : 0.f;
        s[ty + i * 8][tx] = v;
    }
    __syncthreads();
    #pragma unroll
    for (int i = 0; i < 4; i++) {
        int n = n0 + ty + i * 8;
        float v = s[tx][ty + i * 8];
        __nv_bfloat16 h = __float2bfloat16(v);
        size_t o = (size_t)n * K + k0 + tx;
        hi[o] = h;
        lo[o] = __float2bfloat16(v - __bfloat162float(h));
    }
}

// ---------------- TMA-fed tcgen05 GEMM (round-13 proven, cg1, unicast) -------
__global__ __launch_bounds__(GEMM_THREADS, 1) __cluster_dims__(1, 1, 1)
void k_tma_gemm(const __grid_constant__ CUtensorMap mAhi,
                const __grid_constant__ CUtensorMap mAlo,
                const __grid_constant__ CUtensorMap mBhi,
                const __grid_constant__ CUtensorMap mBlo,
                const __nv_bfloat16* __restrict__ Ahi,
                const __nv_bfloat16* __restrict__ Alo,
                const __nv_bfloat16* __restrict__ Bhi,
                const __nv_bfloat16* __restrict__ Blo,
                float* __restrict__ C, int Kd, int Nd) {
    extern __shared__ char smraw[];
#if HAS_TC
    __shared__ uint32_t sh_tmem;
    __shared__ uint64_t sh_bar[4];

    int tid = threadIdx.x, wid = tid >> 5, lane = tid & 31;
    uint32_t raw = smem_u32(smraw);
    uint32_t pad = (1024u - (raw & 1023u)) & 1023u;
    uint32_t smbase = raw + pad;

    uint32_t fullb[2]  = { smem_u32(&sh_bar[0]), smem_u32(&sh_bar[1]) };
    uint32_t emptyb[2] = { smem_u32(&sh_bar[2]), smem_u32(&sh_bar[3]) };
    if (tid == 0) {
        MBARRIER_INIT(fullb[0], 1);  MBARRIER_INIT(fullb[1], 1);
        MBARRIER_INIT(emptyb[0], 1); MBARRIER_INIT(emptyb[1], 1);
    }
    if (wid == 0) { TC_ALLOC(smem_u32(&sh_tmem), 256); TC_RELINQ(); }
    __syncthreads();
    uint32_t tmem = sh_tmem;

    int row0 = blockIdx.y * 128;
    int col0 = blockIdx.x * 256;
    const int NC = Kd >> 6;

    if (wid == 0 && elect1()) {
        int npro = NC < 2 ? NC : 2;
        for (int c = 0; c < npro; c++) {
            uint32_t st = smbase + (uint32_t)c * STAGE_BYTES;
            MBARRIER_EXPECT_TX(fullb[c], STAGE_BYTES);
            TMA_LD2D(st + OFF_AHI, &mAhi, c * 64, row0, fullb[c]);
            TMA_LD2D(st + OFF_ALO, &mAlo, c * 64, row0, fullb[c]);
            TMA_LD2D(st + OFF_BHI, &mBhi, c * 64, col0, fullb[c]);
            TMA_LD2D(st + OFF_BLO, &mBlo, c * 64, col0, fullb[c]);
        }
        for (int c = 0; c < NC; c++) {
            int s = c & 1;
            uint32_t ph = (uint32_t)(c >> 1) & 1u;
            MBAR_WAIT(fullb[s], ph);
            uint32_t sb = smbase + (uint32_t)s * STAGE_BYTES;
            uint64_t dAh = MKDESC(sb + OFF_AHI);
            uint64_t dAl = MKDESC(sb + OFF_ALO);
            uint64_t dBh = MKDESC(sb + OFF_BHI);
            uint64_t dBl = MKDESC(sb + OFF_BLO);
            #pragma unroll
            for (int ks = 0; ks < 4; ++ks) {
                #pragma unroll
                for (int hf = 0; hf < 2; ++hf) {
                    uint32_t d  = tmem + hf * 128;
                    uint64_t ah = dAh + ks * 2;
                    uint64_t al = dAl + ks * 2;
                    uint64_t bh = dBh + hf * 1024 + ks * 2;
                    uint64_t bl = dBl + hf * 1024 + ks * 2;
                    uint32_t en = (c == 0 && ks == 0) ? 0u : 1u;
                    mma_f16_ss(d, ah, bh, IDESC_128, en);
                    mma_f16_ss(d, ah, bl, IDESC_128, 1u);
                    mma_f16_ss(d, al, bh, IDESC_128, 1u);
                }
            }
            TC_COMMIT(emptyb[s]);
            if (c + 2 < NC) {
                MBAR_WAIT(emptyb[s], ph);
                MBARRIER_EXPECT_TX(fullb[s], STAGE_BYTES);
                TMA_LD2D(sb + OFF_AHI, &mAhi, (c + 2) * 64, row0, fullb[s]);
                TMA_LD2D(sb + OFF_ALO, &mAlo, (c + 2) * 64, row0, fullb[s]);
                TMA_LD2D(sb + OFF_BHI, &mBhi, (c + 2) * 64, col0, fullb[s]);
                TMA_LD2D(sb + OFF_BLO, &mBlo, (c + 2) * 64, col0, fullb[s]);
            }
        }
        {
            int sl = (NC - 1) & 1;
            uint32_t phl = (uint32_t)((NC - 1) >> 1) & 1u;
            MBAR_WAIT(emptyb[sl], phl);
        }
    }

    __syncthreads();
    TC_FENCE_AFTER();

    {
        int sub = wid & 3;
        int cb2 = wid >> 2;
        int r = row0 + sub * 32 + lane;
        float* crow = C + (size_t)r * Nd + col0 + cb2 * 64;
        #pragma unroll
        for (int half = 0; half < 2; ++half) {
            uint32_t dr[32];
            TC_LD_X32(dr, tmem + cb2 * 64 + half * 32);
            TC_WAIT_LD();
            #pragma unroll
            for (int q = 0; q < 8; ++q)
                *(uint4*)(crow + half * 32 + q * 4) = *(uint4*)&dr[q * 4];
        }
        TC_FENCE_BEFORE();
    }
    __syncthreads();
    if (wid == 0) TC_DEALLOC(tmem, 256);
#else
    // ---------- FFMA fallback (non-sm_103a compilation pass) ----------
    float* As = (float*)smraw;
    float* Bs = As + 16 * 128;
    int tid  = threadIdx.x;
    int row0 = blockIdx.y * 128;
    int col0 = blockIdx.x * 256;
    int tr = ((tid & 255) >> 4) << 3;
    int tc = (tid & 15) << 3;
    bool active = tid < 256;
    for (int half = 0; half < 2; ++half) {
        int colh = col0 + half * 128;
        float acc[8][8];
        #pragma unroll
        for (int i = 0; i < 8; i++)
            #pragma unroll
            for (int j = 0; j < 8; j++) acc[i][j] = 0.f;
        for (int k0 = 0; k0 < Kd; k0 += 16) {
            if (active) {
                int r = tid >> 1, kk0 = (tid & 1) * 8;
                const __nv_bfloat16* ah = Ahi + (size_t)(row0 + r) * Kd + k0 + kk0;
                const __nv_bfloat16* al = Alo + (size_t)(row0 + r) * Kd + k0 + kk0;
                #pragma unroll
                for (int j = 0; j < 8; j++)
                    As[(kk0 + j) * 128 + r] =
                        __bfloat162float(ah[j]) + __bfloat162float(al[j]);
                const __nv_bfloat16* bhp = Bhi + (size_t)(colh + r) * Kd + k0 + kk0;
                const __nv_bfloat16* blp = Blo + (size_t)(colh + r) * Kd + k0 + kk0;
                #pragma unroll
                for (int j = 0; j < 8; j++)
                    Bs[(kk0 + j) * 128 + r] =
                        __bfloat162float(bhp[j]) + __bfloat162float(blp[j]);
            }
            __syncthreads();
            if (active) {
                #pragma unroll
                for (int kk = 0; kk < 16; kk++) {
                    float av[8], bv[8];
                    #pragma unroll
                    for (int i = 0; i < 8; i++) av[i] = As[kk * 128 + tr + i];
                    #pragma unroll
                    for (int j = 0; j < 8; j++) bv[j] = Bs[kk * 128 + tc + j];
                    #pragma unroll
                    for (int i = 0; i < 8; i++)
                        #pragma unroll
                        for (int j = 0; j < 8; j++)
                            acc[i][j] = fmaf(av[i], bv[j], acc[i][j]);
                }
            }
            __syncthreads();
        }
        if (active) {
            #pragma unroll
            for (int i = 0; i < 8; i++) {
                float* cp = C + (size_t)(row0 + tr + i) * Nd + colh + tc;
                #pragma unroll
                for (int j = 0; j < 8; j++) cp[j] = acc[i][j];
            }
        }
        __syncthreads();
    }
#endif
}

// ---------------- attention coefficients (GAT layers) ----------------
__global__ void k_alpha(const float* __restrict__ xp, int ldx,
                        const float* __restrict__ as_, const float* __restrict__ ad_,
                        float* __restrict__ sv, float* __restrict__ dv, int C, int Hx) {
    int gw = (blockIdx.x * blockDim.x + threadIdx.x) >> 5;
    int lane = threadIdx.x & 31;
    if (gw >= Nn * Hx) return;
    int n = gw / Hx, h = gw % Hx;
    const float* row = xp + (size_t)n * ldx + (size_t)h * C;
    float ss = 0.f, dd = 0.f;
    for (int c = lane; c < C; c += 32) {
        float v = row[c];
        ss = fmaf(v, as_[h * C + c], ss);
        dd = fmaf(v, ad_[h * C + c], dd);
    }
    #pragma unroll
    for (int o = 16; o > 0; o >>= 1) {
        ss += __shfl_down_sync(0xffffffffu, ss, o);
        dd += __shfl_down_sync(0xffffffffu, dd, o);
    }
    if (lane == 0) { sv[n * Hx + h] = ss; dv[n * Hx + h] = dd; }
}

// ---------------- hydra merged alpha: grid.y = k ----------------
__global__ void k_alpha_h(const float* __restrict__ xp,
                          const float* __restrict__ ash, const float* __restrict__ adh,
                          float* __restrict__ sv, float* __restrict__ dv) {
    int k = blockIdx.y;
    int gw = (blockIdx.x * blockDim.x + threadIdx.x) >> 5;
    int lane = threadIdx.x & 31;
    if (gw >= Nn) return;
    const float* row = xp + (size_t)gw * (Kk * 512) + k * 512;
    const float* a_s = ash + k * Mm;
    const float* a_d = adh + k * Mm;
    float ss = 0.f, dd = 0.f;
    for (int c = lane; c < Mm; c += 32) {
        float v = row[c];
        ss = fmaf(v, a_s[c], ss);
        dd = fmaf(v, a_d[c], dd);
    }
    #pragma unroll
    for (int o = 16; o > 0; o >>= 1) {
        ss += __shfl_down_sync(0xffffffffu, ss, o);
        dd += __shfl_down_sync(0xffffffffu, dd, o);
    }
    if (lane == 0) { sv[k * Nn + gw] = ss; dv[k * Nn + gw] = dd; }
}

// ---------------- GAT aggregate + fused softmax + bias + ReLU + LN ----------
#define EB 512
__global__ __launch_bounds__(256) void k_agg_post(const float* __restrict__ xp,
        const float* __restrict__ sv, const float* __restrict__ dv,
        const int* __restrict__ off, const int* __restrict__ csr,
        const float* __restrict__ bias, const float* __restrict__ gamma,
        const float* __restrict__ beta,
        __nv_bfloat16* __restrict__ ohi, __nv_bfloat16* __restrict__ olo, int C) {
    int n = blockIdx.x;
    int beg = off[n], end = off[n + 1];
    int cnt = end - beg;
    int D = Hh * C;
    __shared__ float sha[EB * Hh];
    __shared__ int   ssrc[EB];
    __shared__ float red[256];
    int tid = threadIdx.x, wid = tid >> 5, lane = tid & 31;

    for (int i = tid; i < cnt; i += 256) ssrc[i] = csr[beg + i];
    __syncthreads();

    {   // warp `wid` computes softmax for head `wid`
        int h = wid;
        float dh = dv[n * Hh + h];
        float mm = -1e30f;
        for (int e = lane; e < cnt; e += 32) {
            float v = sv[ssrc[e] * Hh + h] + dh;
            v = v > 0.f ? v : NEGs * v;
            mm = fmaxf(mm, v);
        }
        #pragma unroll
        for (int o = 16; o > 0; o >>= 1)
            mm = fmaxf(mm, __shfl_xor_sync(0xffffffffu, mm, o));
        float z = 0.f;
        for (int e = lane; e < cnt; e += 32) {
            float v = sv[ssrc[e] * Hh + h] + dh;
            v = v > 0.f ? v : NEGs * v;
            z += expf(v - mm);
        }
        #pragma unroll
        for (int o = 16; o > 0; o >>= 1)
            z += __shfl_xor_sync(0xffffffffu, z, o);
        float inv = 1.f / (z + 1e-16f);
        for (int e = lane; e < cnt; e += 32) {
            float v = sv[ssrc[e] * Hh + h] + dh;
            v = v > 0.f ? v : NEGs * v;
            sha[e * Hh + h] = expf(v - mm) * inv;
        }
    }
    __syncthreads();

    float4 acc4[4];
    int    hj4[4];
    #pragma unroll
    for (int i = 0; i < 4; i++) {
        int j = (i << 10) + (tid << 2);
        hj4[i] = (j < D) ? (j / C) : 0;
        acc4[i] = make_float4(0.f, 0.f, 0.f, 0.f);
    }

    for (int e = 0; e < cnt; e++) {
        int sn = ssrc[e];
        const float4* xr = (const float4*)(xp + (size_t)sn * D);
        const float*  al = &sha[e * Hh];
        #pragma unroll
        for (int i = 0; i < 4; i++) {
            int j = (i << 10) + (tid << 2);
            if (j < D) {
                float a = al[hj4[i]];
                float4 v = xr[(i << 8) + tid];
                acc4[i].x = fmaf(a, v.x, acc4[i].x);
                acc4[i].y = fmaf(a, v.y, acc4[i].y);
                acc4[i].z = fmaf(a, v.z, acc4[i].z);
                acc4[i].w = fmaf(a, v.w, acc4[i].w);
            }
        }
    }

    const float4* b4 = (const float4*)bias;
    float lsum = 0.f;
    #pragma unroll
    for (int i = 0; i < 4; i++) {
        int j = (i << 10) + (tid << 2);
        if (j < D) {
            float4 bb = b4[(i << 8) + tid];
            acc4[i].x = fmaxf(acc4[i].x + bb.x, 0.f);
            acc4[i].y = fmaxf(acc4[i].y + bb.y, 0.f);
            acc4[i].z = fmaxf(acc4[i].z + bb.z, 0.f);
            acc4[i].w = fmaxf(acc4[i].w + bb.w, 0.f);
            lsum += acc4[i].x + acc4[i].y + acc4[i].z + acc4[i].w;
        }
    }
    red[tid] = lsum; __syncthreads();
    for (int s2 = 128; s2 > 0; s2 >>= 1) {
        if (tid < s2) red[tid] += red[tid + s2];
        __syncthreads();
    }
    float mean = red[0] / (float)D;
    __syncthreads();
    float lsq = 0.f;
    #pragma unroll
    for (int i = 0; i < 4; i++) {
        int j = (i << 10) + (tid << 2);
        if (j < D) {
            float a = acc4[i].x - mean, b = acc4[i].y - mean;
            float c = acc4[i].z - mean, d = acc4[i].w - mean;
            lsq = fmaf(a, a, lsq); lsq = fmaf(b, b, lsq);
            lsq = fmaf(c, c, lsq); lsq = fmaf(d, d, lsq);
        }
    }
    red[tid] = lsq; __syncthreads();
    for (int s2 = 128; s2 > 0; s2 >>= 1) {
        if (tid < s2) red[tid] += red[tid + s2];
        __syncthreads();
    }
    float rstd = rsqrtf(red[0] / (float)D + LNEPS);
    const float4* g4  = (const float4*)gamma;
    const float4* be4 = (const float4*)beta;
    size_t rowoff = (size_t)n * D;
    #pragma unroll
    for (int i = 0; i < 4; i++) {
        int j = (i << 10) + (tid << 2);
        if (j < D) {
            float4 gg = g4[(i << 8) + tid];
            float4 be = be4[(i << 8) + tid];
            float vv[4] = {
                (acc4[i].x - mean) * rstd * gg.x + be.x,
                (acc4[i].y - mean) * rstd * gg.y + be.y,
                (acc4[i].z - mean) * rstd * gg.z + be.z,
                (acc4[i].w - mean) * rstd * gg.w + be.w
            };
            // pack 4 bf16 into one 8-byte store each for hi and lo
            __nv_bfloat16 h[4];
            uint16_t lo16[4];
            #pragma unroll
            for (int q = 0; q < 4; q++) {
                h[q] = __float2bfloat16(vv[q]);
                __nv_bfloat16 l = __float2bfloat16(vv[q] - __bfloat162float(h[q]));
                lo16[q] = *(uint16_t*)&l;
            }
            uint2 hp, lp;
            hp.x = (uint32_t)(*(uint16_t*)&h[0]) | ((uint32_t)(*(uint16_t*)&h[1]) << 16);
            hp.y = (uint32_t)(*(uint16_t*)&h[2]) | ((uint32_t)(*(uint16_t*)&h[3]) << 16);
            lp.x = (uint32_t)lo16[0] | ((uint32_t)lo16[1] << 16);
            lp.y = (uint32_t)lo16[2] | ((uint32_t)lo16[3] << 16);
            *(uint2*)(ohi + rowoff + j) = hp;
            *(uint2*)(olo + rowoff + j) = lp;
        }
    }
}

// ---------------- hydra aggregate merged, fused softmax: grid = (Nn, Kk) -----
__global__ __launch_bounds__(256) void k_agg_hydra(const float* __restrict__ xp,
        const float* __restrict__ sv, const float* __restrict__ dv,
        const int* __restrict__ off, const int* __restrict__ csr,
        const float* __restrict__ bh, const int* __restrict__ idx,
        float* __restrict__ full, float* __restrict__ ph) {
    int n = blockIdx.x, k = blockIdx.y;
    int beg = off[n], end = off[n + 1];
    int cnt = end - beg;
    __shared__ float sha[EB];
    __shared__ int   ssrc[EB];
    int tid = threadIdx.x, wid = tid >> 5, lane = tid & 31;

    for (int i = tid; i < cnt; i += 256) ssrc[i] = csr[beg + i];
    __syncthreads();

    if (wid == 0) {
        const float* svk = sv + (size_t)k * Nn;
        float dh = dv[(size_t)k * Nn + n];
        float mm = -1e30f;
        for (int e = lane; e < cnt; e += 32) {
            float v = svk[ssrc[e]] + dh;
            v = v > 0.f ? v : NEGs * v;
            mm = fmaxf(mm, v);
        }
        #pragma unroll
        for (int o = 16; o > 0; o >>= 1)
            mm = fmaxf(mm, __shfl_xor_sync(0xffffffffu, mm, o));
        float z = 0.f;
        for (int e = lane; e < cnt; e += 32) {
            float v = svk[ssrc[e]] + dh;
            v = v > 0.f ? v : NEGs * v;
            z += expf(v - mm);
        }
        #pragma unroll
        for (int o = 16; o > 0; o >>= 1)
            z += __shfl_xor_sync(0xffffffffu, z, o);
        float inv = 1.f / (z + 1e-16f);
        for (int e = lane; e < cnt; e += 32) {
            float v = svk[ssrc[e]] + dh;
            v = v > 0.f ? v : NEGs * v;
            sha[e] = expf(v - mm) * inv;
        }
    }
    __syncthreads();

    const float* xpk = xp + k * 512;
    const float* bias = bh + k * Mm;
    const int*  idxk = idx + k * Mm;
    float* phk = ph + (size_t)k * Nn * Mm;
    bool act = tid < 250;
    float2 acc = make_float2(0.f, 0.f);
    for (int e = 0; e < cnt; e++) {
        float a = sha[e];
        if (act) {
            const float2* xr = (const float2*)(xpk + (size_t)ssrc[e] * (Kk * 512));
            float2 v = xr[tid];
            acc.x = fmaf(a, v.x, acc.x);
            acc.y = fmaf(a, v.y, acc.y);
        }
    }
    if (act) {
        int j0 = tid * 2, j1 = j0 + 1;
        float v0 = acc.x + bias[j0];
        float v1 = acc.y + bias[j1];
        phk[(size_t)n * Mm + j0] = v0;
        phk[(size_t)n * Mm + j1] = v1;
        full[(size_t)n * Gg + idxk[j0]] = v0;
        full[(size_t)n * Gg + idxk[j1]] = v1;
    }
}

// ---------------- host: tensor-map encode via driver entry point --------------
typedef CUresult (*EncTiledFn)(CUtensorMap*, CUtensorMapDataType, cuuint32_t, void*,
                               const cuuint64_t*, const cuuint64_t*,
                               const cuuint32_t*, const cuuint32_t*,
                               CUtensorMapInterleave, CUtensorMapSwizzle,
                               CUtensorMapL2promotion, CUtensorMapFloatOOBfill);

static EncTiledFn get_enc() {
    static EncTiledFn fn = nullptr;
    if (!fn) {
        void* p = nullptr;
        cudaDriverEntryPointQueryResult st;
        cudaGetDriverEntryPoint("cuTensorMapEncodeTiled", &p, cudaEnableDefault, &st);
        fn = (EncTiledFn)p;
    }
    return fn;
}

static void enc_map(CUtensorMap* m, void* ptr, uint64_t kd, uint64_t rows,
                    uint32_t box_rows) {
    cuuint64_t dims[2]    = { (cuuint64_t)kd, (cuuint64_t)rows };
    cuuint64_t strides[1] = { (cuuint64_t)(kd * 2) };
    cuuint32_t box[2]     = { 64u, box_rows };
    cuuint32_t es[2]      = { 1u, 1u };
    get_enc()(m, CU_TENSOR_MAP_DATA_TYPE_BFLOAT16, 2, ptr, dims, strides, box, es,
              CU_TENSOR_MAP_INTERLEAVE_NONE, CU_TENSOR_MAP_SWIZZLE_128B,
              CU_TENSOR_MAP_L2_PROMOTION_L2_128B, CU_TENSOR_MAP_FLOAT_OOB_FILL_NONE);
}

// ---------------- host launch ----------------
extern "C" void kernel_launch(void* const* d_in, const int* in_sizes, int n_in,
                              void* d_out, int out_size) {
    const float* x   = (const float*)d_in[0];
    const int*   ei  = (const int*)  d_in[1];
    const float* W1  = (const float*)d_in[2];
    const float* as1 = (const float*)d_in[3];
    const float* ad1 = (const float*)d_in[4];
    const float* b1  = (const float*)d_in[5];
    const float* g1  = (const float*)d_in[6];
    const float* be1 = (const float*)d_in[7];
    const float* W2  = (const float*)d_in[8];
    const float* as2 = (const float*)d_in[9];
    const float* ad2 = (const float*)d_in[10];
    const float* b2  = (const float*)d_in[11];
    const float* g2  = (const float*)d_in[12];
    const float* be2 = (const float*)d_in[13];
    const float* W3  = (const float*)d_in[14];
    const float* as3 = (const float*)d_in[15];
    const float* ad3 = (const float*)d_in[16];
    const float* b3  = (const float*)d_in[17];
    const float* g3  = (const float*)d_in[18];
    const float* be3 = (const float*)d_in[19];
    const float* Wh  = (const float*)d_in[20];
    const float* ash = (const float*)d_in[21];
    const float* adh = (const float*)d_in[22];
    const float* bh  = (const float*)d_in[23];
    const int*   idx = (const int*)  d_in[24];

    int E = in_sizes[1] / 2;
    int Ein = E + Nn;

    void* p;
    cudaGetSymbolAddress(&p, g_xp);  float* d_xp = (float*)p;
    cudaGetSymbolAddress(&p, g_ahi); __nv_bfloat16* d_ahi = (__nv_bfloat16*)p;
    cudaGetSymbolAddress(&p, g_alo); __nv_bfloat16* d_alo = (__nv_bfloat16*)p;
    cudaGetSymbolAddress(&p, g_bhi); __nv_bfloat16* d_bhi = (__nv_bfloat16*)p;
    cudaGetSymbolAddress(&p, g_blo); __nv_bfloat16* d_blo = (__nv_bfloat16*)p;
    cudaGetSymbolAddress(&p, g_s);   float* d_s = (float*)p;
    cudaGetSymbolAddress(&p, g_d);   float* d_d = (float*)p;
    cudaGetSymbolAddress(&p, g_deg); int* d_deg = (int*)p;
    cudaGetSymbolAddress(&p, g_off); int* d_off = (int*)p;
    cudaGetSymbolAddress(&p, g_cur); int* d_cur = (int*)p;
    cudaGetSymbolAddress(&p, g_csr); int* d_csr = (int*)p;

    cudaFuncSetAttribute(k_tma_gemm, cudaFuncAttributeMaxDynamicSharedMemorySize,
                         GEMM_SMEM);

    static cudaStream_t s2 = nullptr;
    static cudaEvent_t evFork, evB[5];
    if (!s2) {
        cudaStreamCreateWithFlags(&s2, cudaStreamNonBlocking);
        cudaEventCreateWithFlags(&evFork, cudaEventDisableTiming);
        for (int i = 0; i < 5; i++)
            cudaEventCreateWithFlags(&evB[i], cudaEventDisableTiming);
    }

    const int D1 = Hh * C1c, D2 = Hh * C2c, D3 = Hh * C3c;
    const int NP = 512;
    dim3 tb(32, 8);
    CUtensorMap mAh, mAl, mBh, mBl;

    __nv_bfloat16* B1h = d_bhi + OFFB1; __nv_bfloat16* B1l = d_blo + OFFB1;
    __nv_bfloat16* B2h = d_bhi + OFFB2; __nv_bfloat16* B2l = d_blo + OFFB2;
    __nv_bfloat16* B3h = d_bhi + OFFB3; __nv_bfloat16* B3l = d_blo + OFFB3;
    __nv_bfloat16* BHh = d_bhi + OFFBH; __nv_bfloat16* BHl = d_blo + OFFBH;

    float* full = (float*)d_out;
    float* pho  = full + (size_t)Nn * Gg;

    cudaEventRecord(evFork, 0);
    cudaStreamWaitEvent(s2, evFork, 0);

    k_wconv_t<<<dim3(D1 / 32, D0c / 32), tb, 0, s2>>>(W1, D0c, D1, B1h, B1l);
    cudaEventRecord(evB[0], s2);

    k_conv_rows<<<1024, 256>>>(x, (size_t)Nn * D0c, d_ahi, d_alo);
    k_init_deg<<<Nn / 256, 256>>>(d_deg);

    enc_map(&mAh, d_ahi, D0c, Nn, 128);
    enc_map(&mAl, d_alo, D0c, Nn, 128);
    enc_map(&mBh, B1h, D0c, D1, 256);
    enc_map(&mBl, B1l, D0c, D1, 256);
    cudaStreamWaitEvent(0, evB[0], 0);
    k_tma_gemm<<<dim3(D1 / 256, Nn / 128), GEMM_THREADS, GEMM_SMEM>>>(
        mAh, mAl, mBh, mBl, d_ahi, d_alo, B1h, B1l, d_xp, D0c, D1);

    k_wconv_t<<<dim3(D2 / 32, D1 / 32), tb, 0, s2>>>(W2, D1, D2, B2h, B2l);
    cudaEventRecord(evB[1], s2);
    k_wconv_t<<<dim3(D3 / 32, D2 / 32), tb, 0, s2>>>(W3, D2, D3, B3h, B3l);
    cudaEventRecord(evB[2], s2);
    for (int k = 0; k < Kk; k++)
        k_wconv_t<<<dim3(NP / 32, D3 / 32), tb, 0, s2>>>(
            Wh + (size_t)k * D3 * Mm, D3, Mm,
            BHh + (size_t)k * NP * D3, BHl + (size_t)k * NP * D3);
    cudaEventRecord(evB[3], s2);
    k_zero_f<<<2048, 256, 0, s2>>>(full, (size_t)Nn * Gg);
    cudaEventRecord(evB[4], s2);

    k_count<<<(E + 255) / 256, 256>>>(ei, E, d_deg);
    k_scan<<<1, 1024>>>(d_deg, d_off);
    k_zero_i<<<Nn / 256, 256>>>(d_cur, Nn);
    k_scatter<<<(Ein + 255) / 256, 256>>>(ei, E, Ein, d_off, d_cur, d_csr);

    k_alpha<<<(Nn * Hh * 32) / 256, 256>>>(d_xp, D1, as1, ad1, d_s, d_d, C1c, Hh);
    k_agg_post<<<Nn, 256>>>(d_xp, d_s, d_d, d_off, d_csr, b1, g1, be1, d_ahi, d_alo, C1c);

    enc_map(&mAh, d_ahi, D1, Nn, 128);
    enc_map(&mAl, d_alo, D1, Nn, 128);
    enc_map(&mBh, B2h, D1, D2, 256);
    enc_map(&mBl, B2l, D1, D2, 256);
    cudaStreamWaitEvent(0, evB[1], 0);
    k_tma_gemm<<<dim3(D2 / 256, Nn / 128), GEMM_THREADS, GEMM_SMEM>>>(
        mAh, mAl, mBh, mBl, d_ahi, d_alo, B2h, B2l, d_xp, D1, D2);
    k_alpha<<<(Nn * Hh * 32) / 256, 256>>>(d_xp, D2, as2, ad2, d_s, d_d, C2c, Hh);
    k_agg_post<<<Nn, 256>>>(d_xp, d_s, d_d, d_off, d_csr, b2, g2, be2, d_ahi, d_alo, C2c);

    enc_map(&mAh, d_ahi, D2, Nn, 128);
    enc_map(&mAl, d_alo, D2, Nn, 128);
    enc_map(&mBh, B3h, D2, D3, 256);
    enc_map(&mBl, B3l, D2, D3, 256);
    cudaStreamWaitEvent(0, evB[2], 0);
    k_tma_gemm<<<dim3(D3 / 256, Nn / 128), GEMM_THREADS, GEMM_SMEM>>>(
        mAh, mAl, mBh, mBl, d_ahi, d_alo, B3h, B3l, d_xp, D2, D3);
    k_alpha<<<(Nn * Hh * 32) / 256, 256>>>(d_xp, D3, as3, ad3, d_s, d_d, C3c, Hh);
    k_agg_post<<<Nn, 256>>>(d_xp, d_s, d_d, d_off, d_csr, b3, g3, be3, d_ahi, d_alo, C3c);

    enc_map(&mAh, d_ahi, D3, Nn, 128);
    enc_map(&mAl, d_alo, D3, Nn, 128);
    enc_map(&mBh, BHh, D3, Kk * NP, 256);
    enc_map(&mBl, BHl, D3, Kk * NP, 256);
    cudaStreamWaitEvent(0, evB[3], 0);
    k_tma_gemm<<<dim3((Kk * NP) / 256, Nn / 128), GEMM_THREADS, GEMM_SMEM>>>(
        mAh, mAl, mBh, mBl, d_ahi, d_alo, BHh, BHl, d_xp, D3, Kk * NP);

    k_alpha_h<<<dim3((Nn * 32) / 256, Kk), 256>>>(d_xp, ash, adh, d_s, d_d);
    cudaStreamWaitEvent(0, evB[4], 0);
    k_agg_hydra<<<dim3(Nn, Kk), 256>>>(d_xp, d_s, d_d, d_off, d_csr, bh, idx,
                                       full, pho);
}

// round 16
// speedup vs baseline: 1.1345x; 1.0343x over previous
#include <cuda_runtime.h>
#include <cuda.h>
#include <cuda_bf16.h>
#include <math.h>
#include <stdint.h>
#include <stddef.h>

// ---------------- problem constants ----------------
#define Nn    4096
#define Hh    8
#define D0c   256
#define C1c   448
#define C2c   384
#define C3c   256
#define Kk    4
#define Mm    500
#define Gg    2000
#define NEGs  0.2f
#define LNEPS 1e-5f
#define MAXD  3584
#define MAXE  40960

// GEMM tiling: BM=128, BN=256, BK=64 per chunk (cg1, bf16 hi/lo 3-pass)
#define STAGE_BYTES 98304u
#define OFF_AHI 0u
#define OFF_ALO 16384u
#define OFF_BHI 32768u
#define OFF_BLO 65536u
#define GEMM_SMEM (2u*STAGE_BYTES + 1024u)
#define GEMM_THREADS 512

// per-layer B-buffer offsets (elements) so wconv can run ahead on stream s2
#define OFFB1 0ull
#define OFFB2 1048576ull
#define OFFB3 12582912ull
#define OFFBH 18874368ull
#define BTOT  23068672ull

#if (defined(__CUDA_ARCH_FEAT_SM103_ALL)) || \
    (defined(__CUDA_ARCH_SPECIFIC__) && (__CUDA_ARCH_SPECIFIC__ == 1030))
#define HAS_TC 1
#else
#define HAS_TC 0
#endif

// ---------------- scratch (device globals) ----------------
__device__ float          g_xp[(size_t)Nn * MAXD];
__device__ __nv_bfloat16  g_ahi[(size_t)Nn * MAXD];
__device__ __nv_bfloat16  g_alo[(size_t)Nn * MAXD];
__device__ __nv_bfloat16  g_bhi[BTOT];
__device__ __nv_bfloat16  g_blo[BTOT];
__device__ float g_s[Kk * Nn * Hh];
__device__ float g_d[Kk * Nn * Hh];
__device__ float g_asf[Kk * 512];
__device__ float g_adf[Kk * 512];
__device__ int   g_deg[Nn];
__device__ int   g_off[Nn + 1];
__device__ int   g_cur[Nn];
__device__ int   g_csr[MAXE];

// ---------------- PTX helpers ----------------
__device__ __forceinline__ uint32_t smem_u32(const void* p) {
    uint32_t a;
    asm("{ .reg .u64 t; cvta.to.shared.u64 t, %1; cvt.u32.u64 %0, t; }"
        : "=r"(a) : "l"(p));
    return a;
}

#if HAS_TC
__device__ __forceinline__ uint32_t elect1() {
    uint32_t p;
    asm volatile("{ .reg .pred p; elect.sync _|p, 0xFFFFFFFF; selp.b32 %0,1,0,p; }"
                 : "=r"(p));
    return p;
}
#define MBARRIER_INIT(addr, cnt) \
    asm volatile("mbarrier.init.shared.b64 [%0], %1;" :: "r"(addr), "r"(cnt) : "memory")
#define MBARRIER_EXPECT_TX(addr, bytes) \
    asm volatile("mbarrier.arrive.expect_tx.shared.b64 _, [%0], %1;" \
                 :: "r"(addr), "r"(bytes) : "memory")

#define MBAR_WAIT(mbar, parity) do {                                          \
    uint32_t _m = (mbar), _p = (parity), _done;                               \
    asm volatile("{\n\t.reg .pred p;\n\t"                                     \
        "mbarrier.try_wait.parity.acquire.cta.shared::cta.b64 p, [%1], %2;\n\t"\
        "selp.b32 %0, 1, 0, p;\n\t}"                                          \
        : "=r"(_done) : "r"(_m), "r"(_p) : "memory");                          \
    if (!_done) {                                                             \
        asm volatile("{\n\t.reg .pred P1;\n\t"                                \
            "WL_%=:\n\t"                                                      \
            "mbarrier.try_wait.parity.acquire.cta.shared::cta.b64 P1, [%0], %1, 0x989680;\n\t" \
            "@P1 bra.uni WD_%=;\n\t"                                          \
            "bra.uni WL_%=;\n\t"                                              \
            "WD_%=:\n\t}"                                                     \
            :: "r"(_m), "r"(_p) : "memory");                                  \
    }                                                                         \
} while (0)

#define TMA_LD2D(dst, map, cx, cy, mb) \
    asm volatile("cp.async.bulk.tensor.2d.shared::cta.global.tile.mbarrier::complete_tx::bytes " \
                 "[%0], [%1, {%2, %3}], [%4];" \
                 :: "r"(dst), "l"(map), "r"(cx), "r"(cy), "r"(mb) : "memory")

#define TC_ALLOC(smaddr, ncols) \
    asm volatile("tcgen05.alloc.cta_group::1.sync.aligned.shared::cta.b32 [%0], %1;" \
                 :: "r"(smaddr), "r"(ncols) : "memory")
#define TC_DEALLOC(tm, ncols) \
    asm volatile("tcgen05.dealloc.cta_group::1.sync.aligned.b32 %0, %1;" :: "r"(tm), "r"(ncols))
#define TC_RELINQ() \
    asm volatile("tcgen05.relinquish_alloc_permit.cta_group::1.sync.aligned;")
#define TC_COMMIT(mb) \
    asm volatile("tcgen05.commit.cta_group::1.mbarrier::arrive::one.shared::cluster.b64 [%0];" \
                 :: "r"(mb) : "memory")
#define TC_FENCE_AFTER()  asm volatile("tcgen05.fence::after_thread_sync;" ::: "memory")
#define TC_FENCE_BEFORE() asm volatile("tcgen05.fence::before_thread_sync;" ::: "memory")
#define TC_WAIT_LD()      asm volatile("tcgen05.wait::ld.sync.aligned;" ::: "memory")

__device__ __forceinline__ void mma_f16_ss(uint32_t d, uint64_t a, uint64_t b,
                                           uint32_t idesc, uint32_t en) {
    asm volatile("{\n\t.reg .pred p;\n\tsetp.ne.u32 p, %5, 0;\n\t"
        "tcgen05.mma.cta_group::1.kind::f16 [%0], %1, %2, %3, {%4,%4,%4,%4}, p;\n\t}"
        :: "r"(d), "l"(a), "l"(b), "r"(idesc), "r"(0u), "r"(en) : "memory");
}

#define TC_LD_X32(r, tm) \
    asm volatile("tcgen05.ld.sync.aligned.32x32b.x32.b32 " \
        "{%0, %1, %2, %3, %4, %5, %6, %7, " \
        " %8, %9, %10, %11, %12, %13, %14, %15, " \
        " %16, %17, %18, %19, %20, %21, %22, %23, " \
        " %24, %25, %26, %27, %28, %29, %30, %31}, [%32];" \
        : "=r"((r)[0]),  "=r"((r)[1]),  "=r"((r)[2]),  "=r"((r)[3]), \
          "=r"((r)[4]),  "=r"((r)[5]),  "=r"((r)[6]),  "=r"((r)[7]), \
          "=r"((r)[8]),  "=r"((r)[9]),  "=r"((r)[10]), "=r"((r)[11]), \
          "=r"((r)[12]), "=r"((r)[13]), "=r"((r)[14]), "=r"((r)[15]), \
          "=r"((r)[16]), "=r"((r)[17]), "=r"((r)[18]), "=r"((r)[19]), \
          "=r"((r)[20]), "=r"((r)[21]), "=r"((r)[22]), "=r"((r)[23]), \
          "=r"((r)[24]), "=r"((r)[25]), "=r"((r)[26]), "=r"((r)[27]), \
          "=r"((r)[28]), "=r"((r)[29]), "=r"((r)[30]), "=r"((r)[31]) \
        : "r"(tm))

#define SDESC_BASE ((2ull << 61) | (1ull << 46) | (64ull << 32) | (1ull << 16))
#define MKDESC(a) (SDESC_BASE | ((uint64_t)((a) >> 4) & 0x3FFFull))

#define IDESC_128 0x08200490u
#endif // HAS_TC

// ---------------- small utility kernels ----------------
__global__ void k_init_deg(int* deg) {
    int i = blockIdx.x * blockDim.x + threadIdx.x;
    if (i < Nn) deg[i] = 1;
}
__global__ void k_count(const int* __restrict__ ei, int E, int* deg) {
    int i = blockIdx.x * blockDim.x + threadIdx.x;
    if (i < E) atomicAdd(&deg[ei[E + i]], 1);
}
__global__ void k_zero_i(int* p, int n) {
    int i = blockIdx.x * blockDim.x + threadIdx.x;
    if (i < n) p[i] = 0;
}
__global__ void k_zero_f(float* p, size_t n) {
    size_t i = (size_t)blockIdx.x * blockDim.x + threadIdx.x;
    size_t stride = (size_t)gridDim.x * blockDim.x;
    for (; i < n; i += stride) p[i] = 0.f;
}
// zero both sv and dv in one launch
__global__ void k_zero_sd(float* sv, float* dv, int n) {
    int i = blockIdx.x * blockDim.x + threadIdx.x;
    if (i < n) { sv[i] = 0.f; dv[i] = 0.f; }
}
__global__ void k_scan(const int* __restrict__ deg, int* __restrict__ off) {
    __shared__ int warp_sums[32];
    int tid = threadIdx.x, lane = tid & 31, wid = tid >> 5;
    int base = tid * 4;
    int v0 = deg[base], v1 = deg[base + 1], v2 = deg[base + 2], v3 = deg[base + 3];
    int t = v0 + v1 + v2 + v3;
    int sc = t;
    #pragma unroll
    for (int o = 1; o < 32; o <<= 1) {
        int u = __shfl_up_sync(0xffffffffu, sc, o);
        if (lane >= o) sc += u;
    }
    if (lane == 31) warp_sums[wid] = sc;
    __syncthreads();
    if (wid == 0) {
        int ws = warp_sums[lane];
        #pragma unroll
        for (int o = 1; o < 32; o <<= 1) {
            int u = __shfl_up_sync(0xffffffffu, ws, o);
            if (lane >= o) ws += u;
        }
        warp_sums[lane] = ws;
    }
    __syncthreads();
    int prefix = sc - t + (wid > 0 ? warp_sums[wid - 1] : 0);
    off[base] = prefix; off[base + 1] = prefix + v0;
    off[base + 2] = prefix + v0 + v1; off[base + 3] = prefix + v0 + v1 + v2;
    if (tid == 1023) off[Nn] = prefix + t;
}
__global__ void k_scatter(const int* __restrict__ ei, int E, int Ein,
                          const int* __restrict__ off, int* __restrict__ cur,
                          int* __restrict__ csr) {
    int e = blockIdx.x * blockDim.x + threadIdx.x;
    if (e >= Ein) return;
    int s, d;
    if (e < E) { s = ei[e]; d = ei[E + e]; }
    else       { s = e - E; d = e - E; }
    int p = atomicAdd(&cur[d], 1);
    csr[off[d] + p] = s;
}

// ---------------- fp32 -> bf16 hi/lo (rows) ----------------
__global__ void k_conv_rows(const float* __restrict__ a, size_t n,
                            __nv_bfloat16* __restrict__ hi,
                            __nv_bfloat16* __restrict__ lo) {
    size_t i = (size_t)blockIdx.x * blockDim.x + threadIdx.x;
    size_t st = (size_t)gridDim.x * blockDim.x;
    for (; i < n; i += st) {
        float v = a[i];
        __nv_bfloat16 h = __float2bfloat16(v);
        hi[i] = h;
        lo[i] = __float2bfloat16(v - __bfloat162float(h));
    }
}

// ---------------- weight convert + transpose ----------------
__global__ void k_wconv_t(const float* __restrict__ W, int K, int N,
                          __nv_bfloat16* __restrict__ hi,
                          __nv_bfloat16* __restrict__ lo) {
    __shared__ float s[32][33];
    int n0 = blockIdx.x * 32, k0 = blockIdx.y * 32;
    int tx = threadIdx.x, ty = threadIdx.y;
    #pragma unroll
    for (int i = 0; i < 4; i++) {
        int k = k0 + ty + i * 8;
        int n = n0 + tx;
        float v = (n < N) ? W[(size_t)k * N + n] : 0.f;
        s[ty + i * 8][tx] = v;
    }
    __syncthreads();
    #pragma unroll
    for (int i = 0; i < 4; i++) {
        int n = n0 + ty + i * 8;
        float v = s[tx][ty + i * 8];
        __nv_bfloat16 h = __float2bfloat16(v);
        size_t o = (size_t)n * K + k0 + tx;
        hi[o] = h;
        lo[o] = __float2bfloat16(v - __bfloat162float(h));
    }
}

// ---------------- hydra a_s/a_d -> flat 512-padded vectors -------------------
__global__ void k_pad_as(const float* __restrict__ ash, const float* __restrict__ adh,
                         float* __restrict__ asf, float* __restrict__ adf) {
    int i = blockIdx.x * blockDim.x + threadIdx.x;   // [0, Kk*512)
    if (i >= Kk * 512) return;
    int k = i >> 9, c = i & 511;
    asf[i] = (c < Mm) ? ash[k * Mm + c] : 0.f;
    adf[i] = (c < Mm) ? adh[k * Mm + c] : 0.f;
}

// ---------------- TMA-fed tcgen05 GEMM + fused alpha dot-products ------------
// Epilogue also accumulates s[n,h]=<xp[n,h,:],a_s[h,:]> (and d) via atomics:
// every 32-col half lies within one head (all C are multiples of 32).
// hmode=0: GAT (sv idx = r*Hh + col/Chead); hmode=1: hydra (idx = (col>>9)*Nn + r).
__global__ __launch_bounds__(GEMM_THREADS, 1) __cluster_dims__(1, 1, 1)
void k_tma_gemm(const __grid_constant__ CUtensorMap mAhi,
                const __grid_constant__ CUtensorMap mAlo,
                const __grid_constant__ CUtensorMap mBhi,
                const __grid_constant__ CUtensorMap mBlo,
                const __nv_bfloat16* __restrict__ Ahi,
                const __nv_bfloat16* __restrict__ Alo,
                const __nv_bfloat16* __restrict__ Bhi,
                const __nv_bfloat16* __restrict__ Blo,
                float* __restrict__ C, int Kd, int Nd,
                const float* __restrict__ asf, const float* __restrict__ adf,
                float* __restrict__ sv, float* __restrict__ dv,
                int hmode, int Chead) {
    extern __shared__ char smraw[];
#if HAS_TC
    __shared__ uint32_t sh_tmem;
    __shared__ uint64_t sh_bar[4];

    int tid = threadIdx.x, wid = tid >> 5, lane = tid & 31;
    uint32_t raw = smem_u32(smraw);
    uint32_t pad = (1024u - (raw & 1023u)) & 1023u;
    uint32_t smbase = raw + pad;

    uint32_t fullb[2]  = { smem_u32(&sh_bar[0]), smem_u32(&sh_bar[1]) };
    uint32_t emptyb[2] = { smem_u32(&sh_bar[2]), smem_u32(&sh_bar[3]) };
    if (tid == 0) {
        MBARRIER_INIT(fullb[0], 1);  MBARRIER_INIT(fullb[1], 1);
        MBARRIER_INIT(emptyb[0], 1); MBARRIER_INIT(emptyb[1], 1);
    }
    if (wid == 0) { TC_ALLOC(smem_u32(&sh_tmem), 256); TC_RELINQ(); }
    __syncthreads();
    uint32_t tmem = sh_tmem;

    int row0 = blockIdx.y * 128;
    int col0 = blockIdx.x * 256;
    const int NC = Kd >> 6;

    if (wid == 0 && elect1()) {
        int npro = NC < 2 ? NC : 2;
        for (int c = 0; c < npro; c++) {
            uint32_t st = smbase + (uint32_t)c * STAGE_BYTES;
            MBARRIER_EXPECT_TX(fullb[c], STAGE_BYTES);
            TMA_LD2D(st + OFF_AHI, &mAhi, c * 64, row0, fullb[c]);
            TMA_LD2D(st + OFF_ALO, &mAlo, c * 64, row0, fullb[c]);
            TMA_LD2D(st + OFF_BHI, &mBhi, c * 64, col0, fullb[c]);
            TMA_LD2D(st + OFF_BLO, &mBlo, c * 64, col0, fullb[c]);
        }
        for (int c = 0; c < NC; c++) {
            int s = c & 1;
            uint32_t ph = (uint32_t)(c >> 1) & 1u;
            MBAR_WAIT(fullb[s], ph);
            uint32_t sb = smbase + (uint32_t)s * STAGE_BYTES;
            uint64_t dAh = MKDESC(sb + OFF_AHI);
            uint64_t dAl = MKDESC(sb + OFF_ALO);
            uint64_t dBh = MKDESC(sb + OFF_BHI);
            uint64_t dBl = MKDESC(sb + OFF_BLO);
            #pragma unroll
            for (int ks = 0; ks < 4; ++ks) {
                #pragma unroll
                for (int hf = 0; hf < 2; ++hf) {
                    uint32_t d  = tmem + hf * 128;
                    uint64_t ah = dAh + ks * 2;
                    uint64_t al = dAl + ks * 2;
                    uint64_t bh = dBh + hf * 1024 + ks * 2;
                    uint64_t bl = dBl + hf * 1024 + ks * 2;
                    uint32_t en = (c == 0 && ks == 0) ? 0u : 1u;
                    mma_f16_ss(d, ah, bh, IDESC_128, en);
                    mma_f16_ss(d, ah, bl, IDESC_128, 1u);
                    mma_f16_ss(d, al, bh, IDESC_128, 1u);
                }
            }
            TC_COMMIT(emptyb[s]);
            if (c + 2 < NC) {
                MBAR_WAIT(emptyb[s], ph);
                MBARRIER_EXPECT_TX(fullb[s], STAGE_BYTES);
                TMA_LD2D(sb + OFF_AHI, &mAhi, (c + 2) * 64, row0, fullb[s]);
                TMA_LD2D(sb + OFF_ALO, &mAlo, (c + 2) * 64, row0, fullb[s]);
                TMA_LD2D(sb + OFF_BHI, &mBhi, (c + 2) * 64, col0, fullb[s]);
                TMA_LD2D(sb + OFF_BLO, &mBlo, (c + 2) * 64, col0, fullb[s]);
            }
        }
        {
            int sl = (NC - 1) & 1;
            uint32_t phl = (uint32_t)((NC - 1) >> 1) & 1u;
            MBAR_WAIT(emptyb[sl], phl);
        }
    }

    __syncthreads();
    TC_FENCE_AFTER();

    {
        int sub = wid & 3;
        int cb2 = wid >> 2;
        int r = row0 + sub * 32 + lane;
        float* crow = C + (size_t)r * Nd + col0 + cb2 * 64;
        #pragma unroll
        for (int half = 0; half < 2; ++half) {
            uint32_t dr[32];
            TC_LD_X32(dr, tmem + cb2 * 64 + half * 32);
            TC_WAIT_LD();
            #pragma unroll
            for (int q = 0; q < 8; ++q)
                *(uint4*)(crow + half * 32 + q * 4) = *(uint4*)&dr[q * 4];
            // fused alpha partial dot for this 32-col block (single head)
            int cbase = col0 + cb2 * 64 + half * 32;
            float accs = 0.f, accd = 0.f;
            #pragma unroll
            for (int q = 0; q < 32; ++q) {
                float v = __uint_as_float(dr[q]);
                accs = fmaf(v, asf[cbase + q], accs);
                accd = fmaf(v, adf[cbase + q], accd);
            }
            int sidx = hmode ? ((cbase >> 9) * Nn + r) : (r * Hh + cbase / Chead);
            atomicAdd(&sv[sidx], accs);
            atomicAdd(&dv[sidx], accd);
        }
        TC_FENCE_BEFORE();
    }
    __syncthreads();
    if (wid == 0) TC_DEALLOC(tmem, 256);
#else
    // ---------- FFMA fallback (non-sm_103a compilation pass) ----------
    float* As = (float*)smraw;
    float* Bs = As + 16 * 128;
    int tid  = threadIdx.x;
    int row0 = blockIdx.y * 128;
    int col0 = blockIdx.x * 256;
    int tr = ((tid & 255) >> 4) << 3;
    int tc = (tid & 15) << 3;
    bool active = tid < 256;
    for (int half = 0; half < 2; ++half) {
        int colh = col0 + half * 128;
        float acc[8][8];
        #pragma unroll
        for (int i = 0; i < 8; i++)
            #pragma unroll
            for (int j = 0; j < 8; j++) acc[i][j] = 0.f;
        for (int k0 = 0; k0 < Kd; k0 += 16) {
            if (active) {
                int r = tid >> 1, kk0 = (tid & 1) * 8;
                const __nv_bfloat16* ah = Ahi + (size_t)(row0 + r) * Kd + k0 + kk0;
                const __nv_bfloat16* al = Alo + (size_t)(row0 + r) * Kd + k0 + kk0;
                #pragma unroll
                for (int j = 0; j < 8; j++)
                    As[(kk0 + j) * 128 + r] =
                        __bfloat162float(ah[j]) + __bfloat162float(al[j]);
                const __nv_bfloat16* bhp = Bhi + (size_t)(colh + r) * Kd + k0 + kk0;
                const __nv_bfloat16* blp = Blo + (size_t)(colh + r) * Kd + k0 + kk0;
                #pragma unroll
                for (int j = 0; j < 8; j++)
                    Bs[(kk0 + j) * 128 + r] =
                        __bfloat162float(bhp[j]) + __bfloat162float(blp[j]);
            }
            __syncthreads();
            if (active) {
                #pragma unroll
                for (int kk = 0; kk < 16; kk++) {
                    float av[8], bv[8];
                    #pragma unroll
                    for (int i = 0; i < 8; i++) av[i] = As[kk * 128 + tr + i];
                    #pragma unroll
                    for (int j = 0; j < 8; j++) bv[j] = Bs[kk * 128 + tc + j];
                    #pragma unroll
                    for (int i = 0; i < 8; i++)
                        #pragma unroll
                        for (int j = 0; j < 8; j++)
                            acc[i][j] = fmaf(av[i], bv[j], acc[i][j]);
                }
            }
            __syncthreads();
        }
        if (active) {
            #pragma unroll
            for (int i = 0; i < 8; i++) {
                int r = row0 + tr + i;
                float* cp = C + (size_t)r * Nd + colh + tc;
                float accs = 0.f, accd = 0.f;
                #pragma unroll
                for (int j = 0; j < 8; j++) {
                    cp[j] = acc[i][j];
                    accs = fmaf(acc[i][j], asf[colh + tc + j], accs);
                    accd = fmaf(acc[i][j], adf[colh + tc + j], accd);
                }
                int cb = colh + tc;   // 8-col window within one head (C%8==0)
                int sidx = hmode ? ((cb >> 9) * Nn + r) : (r * Hh + cb / Chead);
                atomicAdd(&sv[sidx], accs);
                atomicAdd(&dv[sidx], accd);
            }
        }
        __syncthreads();
    }
#endif
}

// ---------------- GAT aggregate + fused softmax + bias + ReLU + LN ----------
#define EB 512
__global__ __launch_bounds__(256) void k_agg_post(const float* __restrict__ xp,
        const float* __restrict__ sv, const float* __restrict__ dv,
        const int* __restrict__ off, const int* __restrict__ csr,
        const float* __restrict__ bias, const float* __restrict__ gamma,
        const float* __restrict__ beta,
        __nv_bfloat16* __restrict__ ohi, __nv_bfloat16* __restrict__ olo, int C) {
    int n = blockIdx.x;
    int beg = off[n], end = off[n + 1];
    int cnt = end - beg;
    int D = Hh * C;
    __shared__ float sha[EB * Hh];
    __shared__ int   ssrc[EB];
    __shared__ float red[256];
    int tid = threadIdx.x, wid = tid >> 5, lane = tid & 31;

    for (int i = tid; i < cnt; i += 256) ssrc[i] = csr[beg + i];
    __syncthreads();

    {   // warp `wid` computes softmax for head `wid`
        int h = wid;
        float dh = dv[n * Hh + h];
        float mm = -1e30f;
        for (int e = lane; e < cnt; e += 32) {
            float v = sv[ssrc[e] * Hh + h] + dh;
            v = v > 0.f ? v : NEGs * v;
            mm = fmaxf(mm, v);
        }
        #pragma unroll
        for (int o = 16; o > 0; o >>= 1)
            mm = fmaxf(mm, __shfl_xor_sync(0xffffffffu, mm, o));
        float z = 0.f;
        for (int e = lane; e < cnt; e += 32) {
            float v = sv[ssrc[e] * Hh + h] + dh;
            v = v > 0.f ? v : NEGs * v;
            z += expf(v - mm);
        }
        #pragma unroll
        for (int o = 16; o > 0; o >>= 1)
            z += __shfl_xor_sync(0xffffffffu, z, o);
        float inv = 1.f / (z + 1e-16f);
        for (int e = lane; e < cnt; e += 32) {
            float v = sv[ssrc[e] * Hh + h] + dh;
            v = v > 0.f ? v : NEGs * v;
            sha[e * Hh + h] = expf(v - mm) * inv;
        }
    }
    __syncthreads();

    float4 acc4[4];
    int    hj4[4];
    #pragma unroll
    for (int i = 0; i < 4; i++) {
        int j = (i << 10) + (tid << 2);
        hj4[i] = (j < D) ? (j / C) : 0;
        acc4[i] = make_float4(0.f, 0.f, 0.f, 0.f);
    }

    for (int e = 0; e < cnt; e++) {
        int sn = ssrc[e];
        const float4* xr = (const float4*)(xp + (size_t)sn * D);
        const float*  al = &sha[e * Hh];
        #pragma unroll
        for (int i = 0; i < 4; i++) {
            int j = (i << 10) + (tid << 2);
            if (j < D) {
                float a = al[hj4[i]];
                float4 v = xr[(i << 8) + tid];
                acc4[i].x = fmaf(a, v.x, acc4[i].x);
                acc4[i].y = fmaf(a, v.y, acc4[i].y);
                acc4[i].z = fmaf(a, v.z, acc4[i].z);
                acc4[i].w = fmaf(a, v.w, acc4[i].w);
            }
        }
    }

    const float4* b4 = (const float4*)bias;
    float lsum = 0.f;
    #pragma unroll
    for (int i = 0; i < 4; i++) {
        int j = (i << 10) + (tid << 2);
        if (j < D) {
            float4 bb = b4[(i << 8) + tid];
            acc4[i].x = fmaxf(acc4[i].x + bb.x, 0.f);
            acc4[i].y = fmaxf(acc4[i].y + bb.y, 0.f);
            acc4[i].z = fmaxf(acc4[i].z + bb.z, 0.f);
            acc4[i].w = fmaxf(acc4[i].w + bb.w, 0.f);
            lsum += acc4[i].x + acc4[i].y + acc4[i].z + acc4[i].w;
        }
    }
    red[tid] = lsum; __syncthreads();
    for (int s2 = 128; s2 > 0; s2 >>= 1) {
        if (tid < s2) red[tid] += red[tid + s2];
        __syncthreads();
    }
    float mean = red[0] / (float)D;
    __syncthreads();
    float lsq = 0.f;
    #pragma unroll
    for (int i = 0; i < 4; i++) {
        int j = (i << 10) + (tid << 2);
        if (j < D) {
            float a = acc4[i].x - mean, b = acc4[i].y - mean;
            float c = acc4[i].z - mean, d = acc4[i].w - mean;
            lsq = fmaf(a, a, lsq); lsq = fmaf(b, b, lsq);
            lsq = fmaf(c, c, lsq); lsq = fmaf(d, d, lsq);
        }
    }
    red[tid] = lsq; __syncthreads();
    for (int s2 = 128; s2 > 0; s2 >>= 1) {
        if (tid < s2) red[tid] += red[tid + s2];
        __syncthreads();
    }
    float rstd = rsqrtf(red[0] / (float)D + LNEPS);
    const float4* g4  = (const float4*)gamma;
    const float4* be4 = (const float4*)beta;
    size_t rowoff = (size_t)n * D;
    #pragma unroll
    for (int i = 0; i < 4; i++) {
        int j = (i << 10) + (tid << 2);
        if (j < D) {
            float4 gg = g4[(i << 8) + tid];
            float4 be = be4[(i << 8) + tid];
            float vv[4] = {
                (acc4[i].x - mean) * rstd * gg.x + be.x,
                (acc4[i].y - mean) * rstd * gg.y + be.y,
                (acc4[i].z - mean) * rstd * gg.z + be.z,
                (acc4[i].w - mean) * rstd * gg.w + be.w
            };
            __nv_bfloat16 h[4];
            uint16_t lo16[4];
            #pragma unroll
            for (int q = 0; q < 4; q++) {
                h[q] = __float2bfloat16(vv[q]);
                __nv_bfloat16 l = __float2bfloat16(vv[q] - __bfloat162float(h[q]));
                lo16[q] = *(uint16_t*)&l;
            }
            uint2 hp, lp;
            hp.x = (uint32_t)(*(uint16_t*)&h[0]) | ((uint32_t)(*(uint16_t*)&h[1]) << 16);
            hp.y = (uint32_t)(*(uint16_t*)&h[2]) | ((uint32_t)(*(uint16_t*)&h[3]) << 16);
            lp.x = (uint32_t)lo16[0] | ((uint32_t)lo16[1] << 16);
            lp.y = (uint32_t)lo16[2] | ((uint32_t)lo16[3] << 16);
            *(uint2*)(ohi + rowoff + j) = hp;
            *(uint2*)(olo + rowoff + j) = lp;
        }
    }
}

// ---------------- hydra aggregate merged, fused softmax: grid = (Nn, Kk) -----
__global__ __launch_bounds__(256) void k_agg_hydra(const float* __restrict__ xp,
        const float* __restrict__ sv, const float* __restrict__ dv,
        const int* __restrict__ off, const int* __restrict__ csr,
        const float* __restrict__ bh, const int* __restrict__ idx,
        float* __restrict__ full, float* __restrict__ ph) {
    int n = blockIdx.x, k = blockIdx.y;
    int beg = off[n], end = off[n + 1];
    int cnt = end - beg;
    __shared__ float sha[EB];
    __shared__ int   ssrc[EB];
    int tid = threadIdx.x, wid = tid >> 5, lane = tid & 31;

    for (int i = tid; i < cnt; i += 256) ssrc[i] = csr[beg + i];
    __syncthreads();

    if (wid == 0) {
        const float* svk = sv + (size_t)k * Nn;
        float dh = dv[(size_t)k * Nn + n];
        float mm = -1e30f;
        for (int e = lane; e < cnt; e += 32) {
            float v = svk[ssrc[e]] + dh;
            v = v > 0.f ? v : NEGs * v;
            mm = fmaxf(mm, v);
        }
        #pragma unroll
        for (int o = 16; o > 0; o >>= 1)
            mm = fmaxf(mm, __shfl_xor_sync(0xffffffffu, mm, o));
        float z = 0.f;
        for (int e = lane; e < cnt; e += 32) {
            float v = svk[ssrc[e]] + dh;
            v = v > 0.f ? v : NEGs * v;
            z += expf(v - mm);
        }
        #pragma unroll
        for (int o = 16; o > 0; o >>= 1)
            z += __shfl_xor_sync(0xffffffffu, z, o);
        float inv = 1.f / (z + 1e-16f);
        for (int e = lane; e < cnt; e += 32) {
            float v = svk[ssrc[e]] + dh;
            v = v > 0.f ? v : NEGs * v;
            sha[e] = expf(v - mm) * inv;
        }
    }
    __syncthreads();

    const float* xpk = xp + k * 512;
    const float* bias = bh + k * Mm;
    const int*  idxk = idx + k * Mm;
    float* phk = ph + (size_t)k * Nn * Mm;
    bool act = tid < 250;
    float2 acc = make_float2(0.f, 0.f);
    for (int e = 0; e < cnt; e++) {
        float a = sha[e];
        if (act) {
            const float2* xr = (const float2*)(xpk + (size_t)ssrc[e] * (Kk * 512));
            float2 v = xr[tid];
            acc.x = fmaf(a, v.x, acc.x);
            acc.y = fmaf(a, v.y, acc.y);
        }
    }
    if (act) {
        int j0 = tid * 2, j1 = j0 + 1;
        float v0 = acc.x + bias[j0];
        float v1 = acc.y + bias[j1];
        phk[(size_t)n * Mm + j0] = v0;
        phk[(size_t)n * Mm + j1] = v1;
        full[(size_t)n * Gg + idxk[j0]] = v0;
        full[(size_t)n * Gg + idxk[j1]] = v1;
    }
}

// ---------------- host: tensor-map encode via driver entry point --------------
typedef CUresult (*EncTiledFn)(CUtensorMap*, CUtensorMapDataType, cuuint32_t, void*,
                               const cuuint64_t*, const cuuint64_t*,
                               const cuuint32_t*, const cuuint32_t*,
                               CUtensorMapInterleave, CUtensorMapSwizzle,
                               CUtensorMapL2promotion, CUtensorMapFloatOOBfill);

static EncTiledFn get_enc() {
    static EncTiledFn fn = nullptr;
    if (!fn) {
        void* p = nullptr;
        cudaDriverEntryPointQueryResult st;
        cudaGetDriverEntryPoint("cuTensorMapEncodeTiled", &p, cudaEnableDefault, &st);
        fn = (EncTiledFn)p;
    }
    return fn;
}

static void enc_map(CUtensorMap* m, void* ptr, uint64_t kd, uint64_t rows,
                    uint32_t box_rows) {
    cuuint64_t dims[2]    = { (cuuint64_t)kd, (cuuint64_t)rows };
    cuuint64_t strides[1] = { (cuuint64_t)(kd * 2) };
    cuuint32_t box[2]     = { 64u, box_rows };
    cuuint32_t es[2]      = { 1u, 1u };
    get_enc()(m, CU_TENSOR_MAP_DATA_TYPE_BFLOAT16, 2, ptr, dims, strides, box, es,
              CU_TENSOR_MAP_INTERLEAVE_NONE, CU_TENSOR_MAP_SWIZZLE_128B,
              CU_TENSOR_MAP_L2_PROMOTION_L2_128B, CU_TENSOR_MAP_FLOAT_OOB_FILL_NONE);
}

// ---------------- host launch ----------------
extern "C" void kernel_launch(void* const* d_in, const int* in_sizes, int n_in,
                              void* d_out, int out_size) {
    const float* x   = (const float*)d_in[0];
    const int*   ei  = (const int*)  d_in[1];
    const float* W1  = (const float*)d_in[2];
    const float* as1 = (const float*)d_in[3];
    const float* ad1 = (const float*)d_in[4];
    const float* b1  = (const float*)d_in[5];
    const float* g1  = (const float*)d_in[6];
    const float* be1 = (const float*)d_in[7];
    const float* W2  = (const float*)d_in[8];
    const float* as2 = (const float*)d_in[9];
    const float* ad2 = (const float*)d_in[10];
    const float* b2  = (const float*)d_in[11];
    const float* g2  = (const float*)d_in[12];
    const float* be2 = (const float*)d_in[13];
    const float* W3  = (const float*)d_in[14];
    const float* as3 = (const float*)d_in[15];
    const float* ad3 = (const float*)d_in[16];
    const float* b3  = (const float*)d_in[17];
    const float* g3  = (const float*)d_in[18];
    const float* be3 = (const float*)d_in[19];
    const float* Wh  = (const float*)d_in[20];
    const float* ash = (const float*)d_in[21];
    const float* adh = (const float*)d_in[22];
    const float* bh  = (const float*)d_in[23];
    const int*   idx = (const int*)  d_in[24];

    int E = in_sizes[1] / 2;
    int Ein = E + Nn;

    void* p;
    cudaGetSymbolAddress(&p, g_xp);  float* d_xp = (float*)p;
    cudaGetSymbolAddress(&p, g_ahi); __nv_bfloat16* d_ahi = (__nv_bfloat16*)p;
    cudaGetSymbolAddress(&p, g_alo); __nv_bfloat16* d_alo = (__nv_bfloat16*)p;
    cudaGetSymbolAddress(&p, g_bhi); __nv_bfloat16* d_bhi = (__nv_bfloat16*)p;
    cudaGetSymbolAddress(&p, g_blo); __nv_bfloat16* d_blo = (__nv_bfloat16*)p;
    cudaGetSymbolAddress(&p, g_s);   float* d_s = (float*)p;
    cudaGetSymbolAddress(&p, g_d);   float* d_d = (float*)p;
    cudaGetSymbolAddress(&p, g_asf); float* d_asf = (float*)p;
    cudaGetSymbolAddress(&p, g_adf); float* d_adf = (float*)p;
    cudaGetSymbolAddress(&p, g_deg); int* d_deg = (int*)p;
    cudaGetSymbolAddress(&p, g_off); int* d_off = (int*)p;
    cudaGetSymbolAddress(&p, g_cur); int* d_cur = (int*)p;
    cudaGetSymbolAddress(&p, g_csr); int* d_csr = (int*)p;

    cudaFuncSetAttribute(k_tma_gemm, cudaFuncAttributeMaxDynamicSharedMemorySize,
                         GEMM_SMEM);

    static cudaStream_t s2 = nullptr;
    static cudaEvent_t evFork, evB[5];
    if (!s2) {
        cudaStreamCreateWithFlags(&s2, cudaStreamNonBlocking);
        cudaEventCreateWithFlags(&evFork, cudaEventDisableTiming);
        for (int i = 0; i < 5; i++)
            cudaEventCreateWithFlags(&evB[i], cudaEventDisableTiming);
    }

    const int D1 = Hh * C1c, D2 = Hh * C2c, D3 = Hh * C3c;
    const int NP = 512;
    dim3 tb(32, 8);
    CUtensorMap mAh, mAl, mBh, mBl;

    __nv_bfloat16* B1h = d_bhi + OFFB1; __nv_bfloat16* B1l = d_blo + OFFB1;
    __nv_bfloat16* B2h = d_bhi + OFFB2; __nv_bfloat16* B2l = d_blo + OFFB2;
    __nv_bfloat16* B3h = d_bhi + OFFB3; __nv_bfloat16* B3l = d_blo + OFFB3;
    __nv_bfloat16* BHh = d_bhi + OFFBH; __nv_bfloat16* BHl = d_blo + OFFBH;

    float* full = (float*)d_out;
    float* pho  = full + (size_t)Nn * Gg;

    cudaEventRecord(evFork, 0);
    cudaStreamWaitEvent(s2, evFork, 0);

    k_wconv_t<<<dim3(D1 / 32, D0c / 32), tb, 0, s2>>>(W1, D0c, D1, B1h, B1l);
    cudaEventRecord(evB[0], s2);

    k_conv_rows<<<1024, 256>>>(x, (size_t)Nn * D0c, d_ahi, d_alo);
    k_init_deg<<<Nn / 256, 256>>>(d_deg);
    k_zero_sd<<<(Nn * Hh) / 256, 256>>>(d_s, d_d, Nn * Hh);

    enc_map(&mAh, d_ahi, D0c, Nn, 128);
    enc_map(&mAl, d_alo, D0c, Nn, 128);
    enc_map(&mBh, B1h, D0c, D1, 256);
    enc_map(&mBl, B1l, D0c, D1, 256);
    cudaStreamWaitEvent(0, evB[0], 0);
    k_tma_gemm<<<dim3(D1 / 256, Nn / 128), GEMM_THREADS, GEMM_SMEM>>>(
        mAh, mAl, mBh, mBl, d_ahi, d_alo, B1h, B1l, d_xp, D0c, D1,
        as1, ad1, d_s, d_d, 0, C1c);

    k_wconv_t<<<dim3(D2 / 32, D1 / 32), tb, 0, s2>>>(W2, D1, D2, B2h, B2l);
    cudaEventRecord(evB[1], s2);
    k_wconv_t<<<dim3(D3 / 32, D2 / 32), tb, 0, s2>>>(W3, D2, D3, B3h, B3l);
    cudaEventRecord(evB[2], s2);
    for (int k = 0; k < Kk; k++)
        k_wconv_t<<<dim3(NP / 32, D3 / 32), tb, 0, s2>>>(
            Wh + (size_t)k * D3 * Mm, D3, Mm,
            BHh + (size_t)k * NP * D3, BHl + (size_t)k * NP * D3);
    k_pad_as<<<(Kk * 512) / 256, 256, 0, s2>>>(ash, adh, d_asf, d_adf);
    cudaEventRecord(evB[3], s2);
    k_zero_f<<<2048, 256, 0, s2>>>(full, (size_t)Nn * Gg);
    cudaEventRecord(evB[4], s2);

    k_count<<<(E + 255) / 256, 256>>>(ei, E, d_deg);
    k_scan<<<1, 1024>>>(d_deg, d_off);
    k_zero_i<<<Nn / 256, 256>>>(d_cur, Nn);
    k_scatter<<<(Ein + 255) / 256, 256>>>(ei, E, Ein, d_off, d_cur, d_csr);

    k_agg_post<<<Nn, 256>>>(d_xp, d_s, d_d, d_off, d_csr, b1, g1, be1, d_ahi, d_alo, C1c);

    k_zero_sd<<<(Nn * Hh) / 256, 256>>>(d_s, d_d, Nn * Hh);
    enc_map(&mAh, d_ahi, D1, Nn, 128);
    enc_map(&mAl, d_alo, D1, Nn, 128);
    enc_map(&mBh, B2h, D1, D2, 256);
    enc_map(&mBl, B2l, D1, D2, 256);
    cudaStreamWaitEvent(0, evB[1], 0);
    k_tma_gemm<<<dim3(D2 / 256, Nn / 128), GEMM_THREADS, GEMM_SMEM>>>(
        mAh, mAl, mBh, mBl, d_ahi, d_alo, B2h, B2l, d_xp, D1, D2,
        as2, ad2, d_s, d_d, 0, C2c);
    k_agg_post<<<Nn, 256>>>(d_xp, d_s, d_d, d_off, d_csr, b2, g2, be2, d_ahi, d_alo, C2c);

    k_zero_sd<<<(Nn * Hh) / 256, 256>>>(d_s, d_d, Nn * Hh);
    enc_map(&mAh, d_ahi, D2, Nn, 128);
    enc_map(&mAl, d_alo, D2, Nn, 128);
    enc_map(&mBh, B3h, D2, D3, 256);
    enc_map(&mBl, B3l, D2, D3, 256);
    cudaStreamWaitEvent(0, evB[2], 0);
    k_tma_gemm<<<dim3(D3 / 256, Nn / 128), GEMM_THREADS, GEMM_SMEM>>>(
        mAh, mAl, mBh, mBl, d_ahi, d_alo, B3h, B3l, d_xp, D2, D3,
        as3, ad3, d_s, d_d, 0, C3c);
    k_agg_post<<<Nn, 256>>>(d_xp, d_s, d_d, d_off, d_csr, b3, g3, be3, d_ahi, d_alo, C3c);

    k_zero_sd<<<(Nn * Hh) / 256, 256>>>(d_s, d_d, Nn * Hh);   // covers Kk*Nn too
    enc_map(&mAh, d_ahi, D3, Nn, 128);
    enc_map(&mAl, d_alo, D3, Nn, 128);
    enc_map(&mBh, BHh, D3, Kk * NP, 256);
    enc_map(&mBl, BHl, D3, Kk * NP, 256);
    cudaStreamWaitEvent(0, evB[3], 0);
    k_tma_gemm<<<dim3((Kk * NP) / 256, Nn / 128), GEMM_THREADS, GEMM_SMEM>>>(
        mAh, mAl, mBh, mBl, d_ahi, d_alo, BHh, BHl, d_xp, D3, Kk * NP,
        d_asf, d_adf, d_s, d_d, 1, NP);

    cudaStreamWaitEvent(0, evB[4], 0);
    k_agg_hydra<<<dim3(Nn, Kk), 256>>>(d_xp, d_s, d_d, d_off, d_csr, bh, idx,
                                       full, pho);
}

// round 17
// speedup vs baseline: 1.1811x; 1.0411x over previous
#include <cuda_runtime.h>
#include <cuda.h>
#include <cuda_bf16.h>
#include <math.h>
#include <stdint.h>
#include <stddef.h>

// ---------------- problem constants ----------------
#define Nn    4096
#define Hh    8
#define D0c   256
#define C1c   448
#define C2c   384
#define C3c   256
#define Kk    4
#define Mm    500
#define Gg    2000
#define NEGs  0.2f
#define LNEPS 1e-5f
#define MAXD  3584
#define MAXE  40960

// GEMM tiling: BM=128, BN=256, BK=64 per chunk (cg1, bf16 hi/lo 3-pass)
#define STAGE_BYTES 98304u
#define OFF_AHI 0u
#define OFF_ALO 16384u
#define OFF_BHI 32768u
#define OFF_BLO 65536u
#define GEMM_SMEM (2u*STAGE_BYTES + 1024u)
#define GEMM_THREADS 512

// per-layer B-buffer offsets (elements) so wconv can run ahead on stream s2
#define OFFB1 0ull
#define OFFB2 1048576ull
#define OFFB3 12582912ull
#define OFFBH 18874368ull
#define BTOT  23068672ull

#if (defined(__CUDA_ARCH_FEAT_SM103_ALL)) || \
    (defined(__CUDA_ARCH_SPECIFIC__) && (__CUDA_ARCH_SPECIFIC__ == 1030))
#define HAS_TC 1
#else
#define HAS_TC 0
#endif

// ---------------- scratch (device globals) ----------------
__device__ float          g_xp[(size_t)Nn * MAXD];
__device__ __nv_bfloat16  g_ahi[(size_t)Nn * MAXD];
__device__ __nv_bfloat16  g_alo[(size_t)Nn * MAXD];
__device__ __nv_bfloat16  g_bhi[BTOT];
__device__ __nv_bfloat16  g_blo[BTOT];
__device__ float g_s[2 * Nn * Hh];     // two buffers (hydra uses Kk*Nn <= Nn*Hh)
__device__ float g_d[2 * Nn * Hh];
__device__ float g_asf[Kk * 512];
__device__ float g_adf[Kk * 512];
__device__ int   g_deg[Nn];
__device__ int   g_off[Nn + 1];
__device__ int   g_cur[Nn];
__device__ int   g_csr[MAXE];

// ---------------- PTX helpers ----------------
__device__ __forceinline__ uint32_t smem_u32(const void* p) {
    uint32_t a;
    asm("{ .reg .u64 t; cvta.to.shared.u64 t, %1; cvt.u32.u64 %0, t; }"
        : "=r"(a) : "l"(p));
    return a;
}

#if HAS_TC
__device__ __forceinline__ uint32_t elect1() {
    uint32_t p;
    asm volatile("{ .reg .pred p; elect.sync _|p, 0xFFFFFFFF; selp.b32 %0,1,0,p; }"
                 : "=r"(p));
    return p;
}
#define MBARRIER_INIT(addr, cnt) \
    asm volatile("mbarrier.init.shared.b64 [%0], %1;" :: "r"(addr), "r"(cnt) : "memory")
#define MBARRIER_EXPECT_TX(addr, bytes) \
    asm volatile("mbarrier.arrive.expect_tx.shared.b64 _, [%0], %1;" \
                 :: "r"(addr), "r"(bytes) : "memory")

#define MBAR_WAIT(mbar, parity) do {                                          \
    uint32_t _m = (mbar), _p = (parity), _done;                               \
    asm volatile("{\n\t.reg .pred p;\n\t"                                     \
        "mbarrier.try_wait.parity.acquire.cta.shared::cta.b64 p, [%1], %2;\n\t"\
        "selp.b32 %0, 1, 0, p;\n\t}"                                          \
        : "=r"(_done) : "r"(_m), "r"(_p) : "memory");                          \
    if (!_done) {                                                             \
        asm volatile("{\n\t.reg .pred P1;\n\t"                                \
            "WL_%=:\n\t"                                                      \
            "mbarrier.try_wait.parity.acquire.cta.shared::cta.b64 P1, [%0], %1, 0x989680;\n\t" \
            "@P1 bra.uni WD_%=;\n\t"                                          \
            "bra.uni WL_%=;\n\t"                                              \
            "WD_%=:\n\t}"                                                     \
            :: "r"(_m), "r"(_p) : "memory");                                  \
    }                                                                         \
} while (0)

#define TMA_LD2D(dst, map, cx, cy, mb) \
    asm volatile("cp.async.bulk.tensor.2d.shared::cta.global.tile.mbarrier::complete_tx::bytes " \
                 "[%0], [%1, {%2, %3}], [%4];" \
                 :: "r"(dst), "l"(map), "r"(cx), "r"(cy), "r"(mb) : "memory")

#define TC_ALLOC(smaddr, ncols) \
    asm volatile("tcgen05.alloc.cta_group::1.sync.aligned.shared::cta.b32 [%0], %1;" \
                 :: "r"(smaddr), "r"(ncols) : "memory")
#define TC_DEALLOC(tm, ncols) \
    asm volatile("tcgen05.dealloc.cta_group::1.sync.aligned.b32 %0, %1;" :: "r"(tm), "r"(ncols))
#define TC_RELINQ() \
    asm volatile("tcgen05.relinquish_alloc_permit.cta_group::1.sync.aligned;")
#define TC_COMMIT(mb) \
    asm volatile("tcgen05.commit.cta_group::1.mbarrier::arrive::one.shared::cluster.b64 [%0];" \
                 :: "r"(mb) : "memory")
#define TC_FENCE_AFTER()  asm volatile("tcgen05.fence::after_thread_sync;" ::: "memory")
#define TC_FENCE_BEFORE() asm volatile("tcgen05.fence::before_thread_sync;" ::: "memory")
#define TC_WAIT_LD()      asm volatile("tcgen05.wait::ld.sync.aligned;" ::: "memory")

__device__ __forceinline__ void mma_f16_ss(uint32_t d, uint64_t a, uint64_t b,
                                           uint32_t idesc, uint32_t en) {
    asm volatile("{\n\t.reg .pred p;\n\tsetp.ne.u32 p, %5, 0;\n\t"
        "tcgen05.mma.cta_group::1.kind::f16 [%0], %1, %2, %3, {%4,%4,%4,%4}, p;\n\t}"
        :: "r"(d), "l"(a), "l"(b), "r"(idesc), "r"(0u), "r"(en) : "memory");
}

#define TC_LD_X32(r, tm) \
    asm volatile("tcgen05.ld.sync.aligned.32x32b.x32.b32 " \
        "{%0, %1, %2, %3, %4, %5, %6, %7, " \
        " %8, %9, %10, %11, %12, %13, %14, %15, " \
        " %16, %17, %18, %19, %20, %21, %22, %23, " \
        " %24, %25, %26, %27, %28, %29, %30, %31}, [%32];" \
        : "=r"((r)[0]),  "=r"((r)[1]),  "=r"((r)[2]),  "=r"((r)[3]), \
          "=r"((r)[4]),  "=r"((r)[5]),  "=r"((r)[6]),  "=r"((r)[7]), \
          "=r"((r)[8]),  "=r"((r)[9]),  "=r"((r)[10]), "=r"((r)[11]), \
          "=r"((r)[12]), "=r"((r)[13]), "=r"((r)[14]), "=r"((r)[15]), \
          "=r"((r)[16]), "=r"((r)[17]), "=r"((r)[18]), "=r"((r)[19]), \
          "=r"((r)[20]), "=r"((r)[21]), "=r"((r)[22]), "=r"((r)[23]), \
          "=r"((r)[24]), "=r"((r)[25]), "=r"((r)[26]), "=r"((r)[27]), \
          "=r"((r)[28]), "=r"((r)[29]), "=r"((r)[30]), "=r"((r)[31]) \
        : "r"(tm))

#define SDESC_BASE ((2ull << 61) | (1ull << 46) | (64ull << 32) | (1ull << 16))
#define MKDESC(a) (SDESC_BASE | ((uint64_t)((a) >> 4) & 0x3FFFull))

#define IDESC_128 0x08200490u
#endif // HAS_TC

// ---------------- small utility kernels ----------------
__global__ void k_init_deg(int* deg) {
    int i = blockIdx.x * blockDim.x + threadIdx.x;
    if (i < Nn) deg[i] = 1;
}
__global__ void k_count(const int* __restrict__ ei, int E, int* deg) {
    int i = blockIdx.x * blockDim.x + threadIdx.x;
    if (i < E) atomicAdd(&deg[ei[E + i]], 1);
}
__global__ void k_zero_i(int* p, int n) {
    int i = blockIdx.x * blockDim.x + threadIdx.x;
    if (i < n) p[i] = 0;
}
__global__ void k_zero_f(float* p, size_t n) {
    size_t i = (size_t)blockIdx.x * blockDim.x + threadIdx.x;
    size_t stride = (size_t)gridDim.x * blockDim.x;
    for (; i < n; i += stride) p[i] = 0.f;
}
__global__ void k_zero_sd(float* sv, float* dv, int n) {
    int i = blockIdx.x * blockDim.x + threadIdx.x;
    if (i < n) { sv[i] = 0.f; dv[i] = 0.f; }
}
__global__ void k_scan(const int* __restrict__ deg, int* __restrict__ off) {
    __shared__ int warp_sums[32];
    int tid = threadIdx.x, lane = tid & 31, wid = tid >> 5;
    int base = tid * 4;
    int v0 = deg[base], v1 = deg[base + 1], v2 = deg[base + 2], v3 = deg[base + 3];
    int t = v0 + v1 + v2 + v3;
    int sc = t;
    #pragma unroll
    for (int o = 1; o < 32; o <<= 1) {
        int u = __shfl_up_sync(0xffffffffu, sc, o);
        if (lane >= o) sc += u;
    }
    if (lane == 31) warp_sums[wid] = sc;
    __syncthreads();
    if (wid == 0) {
        int ws = warp_sums[lane];
        #pragma unroll
        for (int o = 1; o < 32; o <<= 1) {
            int u = __shfl_up_sync(0xffffffffu, ws, o);
            if (lane >= o) ws += u;
        }
        warp_sums[lane] = ws;
    }
    __syncthreads();
    int prefix = sc - t + (wid > 0 ? warp_sums[wid - 1] : 0);
    off[base] = prefix; off[base + 1] = prefix + v0;
    off[base + 2] = prefix + v0 + v1; off[base + 3] = prefix + v0 + v1 + v2;
    if (tid == 1023) off[Nn] = prefix + t;
}
__global__ void k_scatter(const int* __restrict__ ei, int E, int Ein,
                          const int* __restrict__ off, int* __restrict__ cur,
                          int* __restrict__ csr) {
    int e = blockIdx.x * blockDim.x + threadIdx.x;
    if (e >= Ein) return;
    int s, d;
    if (e < E) { s = ei[e]; d = ei[E + e]; }
    else       { s = e - E; d = e - E; }
    int p = atomicAdd(&cur[d], 1);
    csr[off[d] + p] = s;
}

// ---------------- fp32 -> bf16 hi/lo (rows) ----------------
__global__ void k_conv_rows(const float* __restrict__ a, size_t n,
                            __nv_bfloat16* __restrict__ hi,
                            __nv_bfloat16* __restrict__ lo) {
    size_t i = (size_t)blockIdx.x * blockDim.x + threadIdx.x;
    size_t st = (size_t)gridDim.x * blockDim.x;
    for (; i < n; i += st) {
        float v = a[i];
        __nv_bfloat16 h = __float2bfloat16(v);
        hi[i] = h;
        lo[i] = __float2bfloat16(v - __bfloat162float(h));
    }
}

// ---------------- weight convert + transpose ----------------
__global__ void k_wconv_t(const float* __restrict__ W, int K, int N,
                          __nv_bfloat16* __restrict__ hi,
                          __nv_bfloat16* __restrict__ lo) {
    __shared__ float s[32][33];
    int n0 = blockIdx.x * 32, k0 = blockIdx.y * 32;
    int tx = threadIdx.x, ty = threadIdx.y;
    #pragma unroll
    for (int i = 0; i < 4; i++) {
        int k = k0 + ty + i * 8;
        int n = n0 + tx;
        float v = (n < N) ? W[(size_t)k * N + n] : 0.f;
        s[ty + i * 8][tx] = v;
    }
    __syncthreads();
    #pragma unroll
    for (int i = 0; i < 4; i++) {
        int n = n0 + ty + i * 8;
        float v = s[tx][ty + i * 8];
        __nv_bfloat16 h = __float2bfloat16(v);
        size_t o = (size_t)n * K + k0 + tx;
        hi[o] = h;
        lo[o] = __float2bfloat16(v - __bfloat162float(h));
    }
}

// ---------------- hydra a_s/a_d -> flat 512-padded vectors -------------------
__global__ void k_pad_as(const float* __restrict__ ash, const float* __restrict__ adh,
                         float* __restrict__ asf, float* __restrict__ adf) {
    int i = blockIdx.x * blockDim.x + threadIdx.x;   // [0, Kk*512)
    if (i >= Kk * 512) return;
    int k = i >> 9, c = i & 511;
    asf[i] = (c < Mm) ? ash[k * Mm + c] : 0.f;
    adf[i] = (c < Mm) ? adh[k * Mm + c] : 0.f;
}

// ---------------- TMA-fed tcgen05 GEMM + fused alpha dot-products ------------
__global__ __launch_bounds__(GEMM_THREADS, 1) __cluster_dims__(1, 1, 1)
void k_tma_gemm(const __grid_constant__ CUtensorMap mAhi,
                const __grid_constant__ CUtensorMap mAlo,
                const __grid_constant__ CUtensorMap mBhi,
                const __grid_constant__ CUtensorMap mBlo,
                const __nv_bfloat16* __restrict__ Ahi,
                const __nv_bfloat16* __restrict__ Alo,
                const __nv_bfloat16* __restrict__ Bhi,
                const __nv_bfloat16* __restrict__ Blo,
                float* __restrict__ C, int Kd, int Nd,
                const float* __restrict__ asf, const float* __restrict__ adf,
                float* __restrict__ sv, float* __restrict__ dv,
                int hmode, int Chead) {
    extern __shared__ char smraw[];
#if HAS_TC
    __shared__ uint32_t sh_tmem;
    __shared__ uint64_t sh_bar[4];

    int tid = threadIdx.x, wid = tid >> 5, lane = tid & 31;
    uint32_t raw = smem_u32(smraw);
    uint32_t pad = (1024u - (raw & 1023u)) & 1023u;
    uint32_t smbase = raw + pad;

    uint32_t fullb[2]  = { smem_u32(&sh_bar[0]), smem_u32(&sh_bar[1]) };
    uint32_t emptyb[2] = { smem_u32(&sh_bar[2]), smem_u32(&sh_bar[3]) };
    if (tid == 0) {
        MBARRIER_INIT(fullb[0], 1);  MBARRIER_INIT(fullb[1], 1);
        MBARRIER_INIT(emptyb[0], 1); MBARRIER_INIT(emptyb[1], 1);
    }
    if (wid == 0) { TC_ALLOC(smem_u32(&sh_tmem), 256); TC_RELINQ(); }
    __syncthreads();
    uint32_t tmem = sh_tmem;

    int row0 = blockIdx.y * 128;
    int col0 = blockIdx.x * 256;
    const int NC = Kd >> 6;

    if (wid == 0 && elect1()) {
        int npro = NC < 2 ? NC : 2;
        for (int c = 0; c < npro; c++) {
            uint32_t st = smbase + (uint32_t)c * STAGE_BYTES;
            MBARRIER_EXPECT_TX(fullb[c], STAGE_BYTES);
            TMA_LD2D(st + OFF_AHI, &mAhi, c * 64, row0, fullb[c]);
            TMA_LD2D(st + OFF_ALO, &mAlo, c * 64, row0, fullb[c]);
            TMA_LD2D(st + OFF_BHI, &mBhi, c * 64, col0, fullb[c]);
            TMA_LD2D(st + OFF_BLO, &mBlo, c * 64, col0, fullb[c]);
        }
        for (int c = 0; c < NC; c++) {
            int s = c & 1;
            uint32_t ph = (uint32_t)(c >> 1) & 1u;
            MBAR_WAIT(fullb[s], ph);
            uint32_t sb = smbase + (uint32_t)s * STAGE_BYTES;
            uint64_t dAh = MKDESC(sb + OFF_AHI);
            uint64_t dAl = MKDESC(sb + OFF_ALO);
            uint64_t dBh = MKDESC(sb + OFF_BHI);
            uint64_t dBl = MKDESC(sb + OFF_BLO);
            #pragma unroll
            for (int ks = 0; ks < 4; ++ks) {
                #pragma unroll
                for (int hf = 0; hf < 2; ++hf) {
                    uint32_t d  = tmem + hf * 128;
                    uint64_t ah = dAh + ks * 2;
                    uint64_t al = dAl + ks * 2;
                    uint64_t bh = dBh + hf * 1024 + ks * 2;
                    uint64_t bl = dBl + hf * 1024 + ks * 2;
                    uint32_t en = (c == 0 && ks == 0) ? 0u : 1u;
                    mma_f16_ss(d, ah, bh, IDESC_128, en);
                    mma_f16_ss(d, ah, bl, IDESC_128, 1u);
                    mma_f16_ss(d, al, bh, IDESC_128, 1u);
                }
            }
            TC_COMMIT(emptyb[s]);
            if (c + 2 < NC) {
                MBAR_WAIT(emptyb[s], ph);
                MBARRIER_EXPECT_TX(fullb[s], STAGE_BYTES);
                TMA_LD2D(sb + OFF_AHI, &mAhi, (c + 2) * 64, row0, fullb[s]);
                TMA_LD2D(sb + OFF_ALO, &mAlo, (c + 2) * 64, row0, fullb[s]);
                TMA_LD2D(sb + OFF_BHI, &mBhi, (c + 2) * 64, col0, fullb[s]);
                TMA_LD2D(sb + OFF_BLO, &mBlo, (c + 2) * 64, col0, fullb[s]);
            }
        }
        {
            int sl = (NC - 1) & 1;
            uint32_t phl = (uint32_t)((NC - 1) >> 1) & 1u;
            MBAR_WAIT(emptyb[sl], phl);
        }
    }

    __syncthreads();
    TC_FENCE_AFTER();

    {
        int sub = wid & 3;
        int cb2 = wid >> 2;
        int r = row0 + sub * 32 + lane;
        float* crow = C + (size_t)r * Nd + col0 + cb2 * 64;
        #pragma unroll
        for (int half = 0; half < 2; ++half) {
            uint32_t dr[32];
            TC_LD_X32(dr, tmem + cb2 * 64 + half * 32);
            TC_WAIT_LD();
            #pragma unroll
            for (int q = 0; q < 8; ++q)
                *(uint4*)(crow + half * 32 + q * 4) = *(uint4*)&dr[q * 4];
            int cbase = col0 + cb2 * 64 + half * 32;
            float accs = 0.f, accd = 0.f;
            #pragma unroll
            for (int q = 0; q < 32; ++q) {
                float v = __uint_as_float(dr[q]);
                accs = fmaf(v, asf[cbase + q], accs);
                accd = fmaf(v, adf[cbase + q], accd);
            }
            int sidx = hmode ? ((cbase >> 9) * Nn + r) : (r * Hh + cbase / Chead);
            atomicAdd(&sv[sidx], accs);
            atomicAdd(&dv[sidx], accd);
        }
        TC_FENCE_BEFORE();
    }
    __syncthreads();
    if (wid == 0) TC_DEALLOC(tmem, 256);
#else
    // ---------- FFMA fallback (non-sm_103a compilation pass) ----------
    float* As = (float*)smraw;
    float* Bs = As + 16 * 128;
    int tid  = threadIdx.x;
    int row0 = blockIdx.y * 128;
    int col0 = blockIdx.x * 256;
    int tr = ((tid & 255) >> 4) << 3;
    int tc = (tid & 15) << 3;
    bool active = tid < 256;
    for (int half = 0; half < 2; ++half) {
        int colh = col0 + half * 128;
        float acc[8][8];
        #pragma unroll
        for (int i = 0; i < 8; i++)
            #pragma unroll
            for (int j = 0; j < 8; j++) acc[i][j] = 0.f;
        for (int k0 = 0; k0 < Kd; k0 += 16) {
            if (active) {
                int r = tid >> 1, kk0 = (tid & 1) * 8;
                const __nv_bfloat16* ah = Ahi + (size_t)(row0 + r) * Kd + k0 + kk0;
                const __nv_bfloat16* al = Alo + (size_t)(row0 + r) * Kd + k0 + kk0;
                #pragma unroll
                for (int j = 0; j < 8; j++)
                    As[(kk0 + j) * 128 + r] =
                        __bfloat162float(ah[j]) + __bfloat162float(al[j]);
                const __nv_bfloat16* bhp = Bhi + (size_t)(colh + r) * Kd + k0 + kk0;
                const __nv_bfloat16* blp = Blo + (size_t)(colh + r) * Kd + k0 + kk0;
                #pragma unroll
                for (int j = 0; j < 8; j++)
                    Bs[(kk0 + j) * 128 + r] =
                        __bfloat162float(bhp[j]) + __bfloat162float(blp[j]);
            }
            __syncthreads();
            if (active) {
                #pragma unroll
                for (int kk = 0; kk < 16; kk++) {
                    float av[8], bv[8];
                    #pragma unroll
                    for (int i = 0; i < 8; i++) av[i] = As[kk * 128 + tr + i];
                    #pragma unroll
                    for (int j = 0; j < 8; j++) bv[j] = Bs[kk * 128 + tc + j];
                    #pragma unroll
                    for (int i = 0; i < 8; i++)
                        #pragma unroll
                        for (int j = 0; j < 8; j++)
                            acc[i][j] = fmaf(av[i], bv[j], acc[i][j]);
                }
            }
            __syncthreads();
        }
        if (active) {
            #pragma unroll
            for (int i = 0; i < 8; i++) {
                int r = row0 + tr + i;
                float* cp = C + (size_t)r * Nd + colh + tc;
                float accs = 0.f, accd = 0.f;
                #pragma unroll
                for (int j = 0; j < 8; j++) {
                    cp[j] = acc[i][j];
                    accs = fmaf(acc[i][j], asf[colh + tc + j], accs);
                    accd = fmaf(acc[i][j], adf[colh + tc + j], accd);
                }
                int cb = colh + tc;
                int sidx = hmode ? ((cb >> 9) * Nn + r) : (r * Hh + cb / Chead);
                atomicAdd(&sv[sidx], accs);
                atomicAdd(&dv[sidx], accd);
            }
        }
        __syncthreads();
    }
#endif
}

// ---------------- GAT aggregate + fused softmax + bias + ReLU + LN ----------
#define EB 512
__global__ __launch_bounds__(256) void k_agg_post(const float* __restrict__ xp,
        const float* __restrict__ sv, const float* __restrict__ dv,
        const int* __restrict__ off, const int* __restrict__ csr,
        const float* __restrict__ bias, const float* __restrict__ gamma,
        const float* __restrict__ beta,
        __nv_bfloat16* __restrict__ ohi, __nv_bfloat16* __restrict__ olo, int C) {
    int n = blockIdx.x;
    int beg = off[n], end = off[n + 1];
    int cnt = end - beg;
    int D = Hh * C;
    __shared__ float sha[EB * Hh];
    __shared__ int   ssrc[EB];
    __shared__ float red[256];
    int tid = threadIdx.x, wid = tid >> 5, lane = tid & 31;

    for (int i = tid; i < cnt; i += 256) ssrc[i] = csr[beg + i];
    __syncthreads();

    {   // warp `wid` computes softmax for head `wid`
        int h = wid;
        float dh = dv[n * Hh + h];
        float mm = -1e30f;
        for (int e = lane; e < cnt; e += 32) {
            float v = sv[ssrc[e] * Hh + h] + dh;
            v = v > 0.f ? v : NEGs * v;
            mm = fmaxf(mm, v);
        }
        #pragma unroll
        for (int o = 16; o > 0; o >>= 1)
            mm = fmaxf(mm, __shfl_xor_sync(0xffffffffu, mm, o));
        float z = 0.f;
        for (int e = lane; e < cnt; e += 32) {
            float v = sv[ssrc[e] * Hh + h] + dh;
            v = v > 0.f ? v : NEGs * v;
            z += expf(v - mm);
        }
        #pragma unroll
        for (int o = 16; o > 0; o >>= 1)
            z += __shfl_xor_sync(0xffffffffu, z, o);
        float inv = 1.f / (z + 1e-16f);
        for (int e = lane; e < cnt; e += 32) {
            float v = sv[ssrc[e] * Hh + h] + dh;
            v = v > 0.f ? v : NEGs * v;
            sha[e * Hh + h] = expf(v - mm) * inv;
        }
    }
    __syncthreads();

    float4 acc4[4];
    int    hj4[4];
    #pragma unroll
    for (int i = 0; i < 4; i++) {
        int j = (i << 10) + (tid << 2);
        hj4[i] = (j < D) ? (j / C) : 0;
        acc4[i] = make_float4(0.f, 0.f, 0.f, 0.f);
    }

    for (int e = 0; e < cnt; e++) {
        int sn = ssrc[e];
        const float4* xr = (const float4*)(xp + (size_t)sn * D);
        const float*  al = &sha[e * Hh];
        #pragma unroll
        for (int i = 0; i < 4; i++) {
            int j = (i << 10) + (tid << 2);
            if (j < D) {
                float a = al[hj4[i]];
                float4 v = xr[(i << 8) + tid];
                acc4[i].x = fmaf(a, v.x, acc4[i].x);
                acc4[i].y = fmaf(a, v.y, acc4[i].y);
                acc4[i].z = fmaf(a, v.z, acc4[i].z);
                acc4[i].w = fmaf(a, v.w, acc4[i].w);
            }
        }
    }

    const float4* b4 = (const float4*)bias;
    float lsum = 0.f;
    #pragma unroll
    for (int i = 0; i < 4; i++) {
        int j = (i << 10) + (tid << 2);
        if (j < D) {
            float4 bb = b4[(i << 8) + tid];
            acc4[i].x = fmaxf(acc4[i].x + bb.x, 0.f);
            acc4[i].y = fmaxf(acc4[i].y + bb.y, 0.f);
            acc4[i].z = fmaxf(acc4[i].z + bb.z, 0.f);
            acc4[i].w = fmaxf(acc4[i].w + bb.w, 0.f);
            lsum += acc4[i].x + acc4[i].y + acc4[i].z + acc4[i].w;
        }
    }
    red[tid] = lsum; __syncthreads();
    for (int s2 = 128; s2 > 0; s2 >>= 1) {
        if (tid < s2) red[tid] += red[tid + s2];
        __syncthreads();
    }
    float mean = red[0] / (float)D;
    __syncthreads();
    float lsq = 0.f;
    #pragma unroll
    for (int i = 0; i < 4; i++) {
        int j = (i << 10) + (tid << 2);
        if (j < D) {
            float a = acc4[i].x - mean, b = acc4[i].y - mean;
            float c = acc4[i].z - mean, d = acc4[i].w - mean;
            lsq = fmaf(a, a, lsq); lsq = fmaf(b, b, lsq);
            lsq = fmaf(c, c, lsq); lsq = fmaf(d, d, lsq);
        }
    }
    red[tid] = lsq; __syncthreads();
    for (int s2 = 128; s2 > 0; s2 >>= 1) {
        if (tid < s2) red[tid] += red[tid + s2];
        __syncthreads();
    }
    float rstd = rsqrtf(red[0] / (float)D + LNEPS);
    const float4* g4  = (const float4*)gamma;
    const float4* be4 = (const float4*)beta;
    size_t rowoff = (size_t)n * D;
    #pragma unroll
    for (int i = 0; i < 4; i++) {
        int j = (i << 10) + (tid << 2);
        if (j < D) {
            float4 gg = g4[(i << 8) + tid];
            float4 be = be4[(i << 8) + tid];
            float vv[4] = {
                (acc4[i].x - mean) * rstd * gg.x + be.x,
                (acc4[i].y - mean) * rstd * gg.y + be.y,
                (acc4[i].z - mean) * rstd * gg.z + be.z,
                (acc4[i].w - mean) * rstd * gg.w + be.w
            };
            __nv_bfloat16 h[4];
            uint16_t lo16[4];
            #pragma unroll
            for (int q = 0; q < 4; q++) {
                h[q] = __float2bfloat16(vv[q]);
                __nv_bfloat16 l = __float2bfloat16(vv[q] - __bfloat162float(h[q]));
                lo16[q] = *(uint16_t*)&l;
            }
            uint2 hp, lp;
            hp.x = (uint32_t)(*(uint16_t*)&h[0]) | ((uint32_t)(*(uint16_t*)&h[1]) << 16);
            hp.y = (uint32_t)(*(uint16_t*)&h[2]) | ((uint32_t)(*(uint16_t*)&h[3]) << 16);
            lp.x = (uint32_t)lo16[0] | ((uint32_t)lo16[1] << 16);
            lp.y = (uint32_t)lo16[2] | ((uint32_t)lo16[3] << 16);
            *(uint2*)(ohi + rowoff + j) = hp;
            *(uint2*)(olo + rowoff + j) = lp;
        }
    }
}

// ---------------- hydra aggregate: ALL 4 heads in one block per node ---------
__global__ __launch_bounds__(256) void k_agg_hydra(const float* __restrict__ xp,
        const float* __restrict__ sv, const float* __restrict__ dv,
        const int* __restrict__ off, const int* __restrict__ csr,
        const float* __restrict__ bh, const int* __restrict__ idx,
        float* __restrict__ full, float* __restrict__ ph) {
    int n = blockIdx.x;
    int beg = off[n], end = off[n + 1];
    int cnt = end - beg;
    __shared__ float sha[Kk * EB];
    __shared__ int   ssrc[EB];
    int tid = threadIdx.x, wid = tid >> 5, lane = tid & 31;

    for (int i = tid; i < cnt; i += 256) ssrc[i] = csr[beg + i];
    __syncthreads();

    if (wid < Kk) {   // warp k computes softmax for head k
        int k = wid;
        const float* svk = sv + (size_t)k * Nn;
        float dh = dv[(size_t)k * Nn + n];
        float mm = -1e30f;
        for (int e = lane; e < cnt; e += 32) {
            float v = svk[ssrc[e]] + dh;
            v = v > 0.f ? v : NEGs * v;
            mm = fmaxf(mm, v);
        }
        #pragma unroll
        for (int o = 16; o > 0; o >>= 1)
            mm = fmaxf(mm, __shfl_xor_sync(0xffffffffu, mm, o));
        float z = 0.f;
        for (int e = lane; e < cnt; e += 32) {
            float v = svk[ssrc[e]] + dh;
            v = v > 0.f ? v : NEGs * v;
            z += expf(v - mm);
        }
        #pragma unroll
        for (int o = 16; o > 0; o >>= 1)
            z += __shfl_xor_sync(0xffffffffu, z, o);
        float inv = 1.f / (z + 1e-16f);
        for (int e = lane; e < cnt; e += 32) {
            float v = svk[ssrc[e]] + dh;
            v = v > 0.f ? v : NEGs * v;
            sha[k * EB + e] = expf(v - mm) * inv;
        }
    }
    __syncthreads();

    bool act = tid < 250;
    float2 acc[Kk];
    #pragma unroll
    for (int k = 0; k < Kk; k++) acc[k] = make_float2(0.f, 0.f);
    for (int e = 0; e < cnt; e++) {
        const float2* xr = (const float2*)(xp + (size_t)ssrc[e] * (Kk * 512));
        if (act) {
            #pragma unroll
            for (int k = 0; k < Kk; k++) {
                float a = sha[k * EB + e];
                float2 v = xr[k * 256 + tid];
                acc[k].x = fmaf(a, v.x, acc[k].x);
                acc[k].y = fmaf(a, v.y, acc[k].y);
            }
        }
    }
    if (act) {
        #pragma unroll
        for (int k = 0; k < Kk; k++) {
            int j0 = tid * 2, j1 = j0 + 1;
            float v0 = acc[k].x + bh[k * Mm + j0];
            float v1 = acc[k].y + bh[k * Mm + j1];
            float* phk = ph + (size_t)k * Nn * Mm;
            phk[(size_t)n * Mm + j0] = v0;
            phk[(size_t)n * Mm + j1] = v1;
            full[(size_t)n * Gg + idx[k * Mm + j0]] = v0;
            full[(size_t)n * Gg + idx[k * Mm + j1]] = v1;
        }
    }
}

// ---------------- host: tensor-map encode via driver entry point --------------
typedef CUresult (*EncTiledFn)(CUtensorMap*, CUtensorMapDataType, cuuint32_t, void*,
                               const cuuint64_t*, const cuuint64_t*,
                               const cuuint32_t*, const cuuint32_t*,
                               CUtensorMapInterleave, CUtensorMapSwizzle,
                               CUtensorMapL2promotion, CUtensorMapFloatOOBfill);

static EncTiledFn get_enc() {
    static EncTiledFn fn = nullptr;
    if (!fn) {
        void* p = nullptr;
        cudaDriverEntryPointQueryResult st;
        cudaGetDriverEntryPoint("cuTensorMapEncodeTiled", &p, cudaEnableDefault, &st);
        fn = (EncTiledFn)p;
    }
    return fn;
}

static void enc_map(CUtensorMap* m, void* ptr, uint64_t kd, uint64_t rows,
                    uint32_t box_rows) {
    cuuint64_t dims[2]    = { (cuuint64_t)kd, (cuuint64_t)rows };
    cuuint64_t strides[1] = { (cuuint64_t)(kd * 2) };
    cuuint32_t box[2]     = { 64u, box_rows };
    cuuint32_t es[2]      = { 1u, 1u };
    get_enc()(m, CU_TENSOR_MAP_DATA_TYPE_BFLOAT16, 2, ptr, dims, strides, box, es,
              CU_TENSOR_MAP_INTERLEAVE_NONE, CU_TENSOR_MAP_SWIZZLE_128B,
              CU_TENSOR_MAP_L2_PROMOTION_L2_128B, CU_TENSOR_MAP_FLOAT_OOB_FILL_NONE);
}

// ---------------- host launch ----------------
extern "C" void kernel_launch(void* const* d_in, const int* in_sizes, int n_in,
                              void* d_out, int out_size) {
    const float* x   = (const float*)d_in[0];
    const int*   ei  = (const int*)  d_in[1];
    const float* W1  = (const float*)d_in[2];
    const float* as1 = (const float*)d_in[3];
    const float* ad1 = (const float*)d_in[4];
    const float* b1  = (const float*)d_in[5];
    const float* g1  = (const float*)d_in[6];
    const float* be1 = (const float*)d_in[7];
    const float* W2  = (const float*)d_in[8];
    const float* as2 = (const float*)d_in[9];
    const float* ad2 = (const float*)d_in[10];
    const float* b2  = (const float*)d_in[11];
    const float* g2  = (const float*)d_in[12];
    const float* be2 = (const float*)d_in[13];
    const float* W3  = (const float*)d_in[14];
    const float* as3 = (const float*)d_in[15];
    const float* ad3 = (const float*)d_in[16];
    const float* b3  = (const float*)d_in[17];
    const float* g3  = (const float*)d_in[18];
    const float* be3 = (const float*)d_in[19];
    const float* Wh  = (const float*)d_in[20];
    const float* ash = (const float*)d_in[21];
    const float* adh = (const float*)d_in[22];
    const float* bh  = (const float*)d_in[23];
    const int*   idx = (const int*)  d_in[24];

    int E = in_sizes[1] / 2;
    int Ein = E + Nn;

    void* p;
    cudaGetSymbolAddress(&p, g_xp);  float* d_xp = (float*)p;
    cudaGetSymbolAddress(&p, g_ahi); __nv_bfloat16* d_ahi = (__nv_bfloat16*)p;
    cudaGetSymbolAddress(&p, g_alo); __nv_bfloat16* d_alo = (__nv_bfloat16*)p;
    cudaGetSymbolAddress(&p, g_bhi); __nv_bfloat16* d_bhi = (__nv_bfloat16*)p;
    cudaGetSymbolAddress(&p, g_blo); __nv_bfloat16* d_blo = (__nv_bfloat16*)p;
    cudaGetSymbolAddress(&p, g_s);   float* d_s = (float*)p;
    cudaGetSymbolAddress(&p, g_d);   float* d_d = (float*)p;
    cudaGetSymbolAddress(&p, g_asf); float* d_asf = (float*)p;
    cudaGetSymbolAddress(&p, g_adf); float* d_adf = (float*)p;
    cudaGetSymbolAddress(&p, g_deg); int* d_deg = (int*)p;
    cudaGetSymbolAddress(&p, g_off); int* d_off = (int*)p;
    cudaGetSymbolAddress(&p, g_cur); int* d_cur = (int*)p;
    cudaGetSymbolAddress(&p, g_csr); int* d_csr = (int*)p;

    // sv/dv double buffers
    float* sv0 = d_s;               float* dv0 = d_d;
    float* sv1 = d_s + Nn * Hh;     float* dv1 = d_d + Nn * Hh;

    cudaFuncSetAttribute(k_tma_gemm, cudaFuncAttributeMaxDynamicSharedMemorySize,
                         GEMM_SMEM);

    static cudaStream_t s2 = nullptr;
    static cudaEvent_t evFork, evB[5], evCSR, evA1, evA2, evZ2, evZ3;
    if (!s2) {
        cudaStreamCreateWithFlags(&s2, cudaStreamNonBlocking);
        cudaEventCreateWithFlags(&evFork, cudaEventDisableTiming);
        for (int i = 0; i < 5; i++)
            cudaEventCreateWithFlags(&evB[i], cudaEventDisableTiming);
        cudaEventCreateWithFlags(&evCSR, cudaEventDisableTiming);
        cudaEventCreateWithFlags(&evA1, cudaEventDisableTiming);
        cudaEventCreateWithFlags(&evA2, cudaEventDisableTiming);
        cudaEventCreateWithFlags(&evZ2, cudaEventDisableTiming);
        cudaEventCreateWithFlags(&evZ3, cudaEventDisableTiming);
    }

    const int D1 = Hh * C1c, D2 = Hh * C2c, D3 = Hh * C3c;
    const int NP = 512;
    dim3 tb(32, 8);
    CUtensorMap mAh, mAl, mBh, mBl;

    __nv_bfloat16* B1h = d_bhi + OFFB1; __nv_bfloat16* B1l = d_blo + OFFB1;
    __nv_bfloat16* B2h = d_bhi + OFFB2; __nv_bfloat16* B2l = d_blo + OFFB2;
    __nv_bfloat16* B3h = d_bhi + OFFB3; __nv_bfloat16* B3l = d_blo + OFFB3;
    __nv_bfloat16* BHh = d_bhi + OFFBH; __nv_bfloat16* BHl = d_blo + OFFBH;

    float* full = (float*)d_out;
    float* pho  = full + (size_t)Nn * Gg;

    cudaEventRecord(evFork, 0);
    cudaStreamWaitEvent(s2, evFork, 0);

    // s2: B1 conversion + both sv/dv buffer zeros (GEMM1 gate)
    k_wconv_t<<<dim3(D1 / 32, D0c / 32), tb, 0, s2>>>(W1, D0c, D1, B1h, B1l);
    k_zero_sd<<<(Nn * Hh) / 256, 256, 0, s2>>>(sv0, dv0, Nn * Hh);
    k_zero_sd<<<(Nn * Hh) / 256, 256, 0, s2>>>(sv1, dv1, Nn * Hh);
    cudaEventRecord(evB[0], s2);

    // s2: CSR build (only depends on ei) — overlaps GEMM1
    k_init_deg<<<Nn / 256, 256, 0, s2>>>(d_deg);
    k_count<<<(E + 255) / 256, 256, 0, s2>>>(ei, E, d_deg);
    k_scan<<<1, 1024, 0, s2>>>(d_deg, d_off);
    k_zero_i<<<Nn / 256, 256, 0, s2>>>(d_cur, Nn);
    k_scatter<<<(Ein + 255) / 256, 256, 0, s2>>>(ei, E, Ein, d_off, d_cur, d_csr);
    cudaEventRecord(evCSR, s2);

    // main: activation conversion, then GEMM1 (-> sv0)
    k_conv_rows<<<1024, 256>>>(x, (size_t)Nn * D0c, d_ahi, d_alo);
    enc_map(&mAh, d_ahi, D0c, Nn, 128);
    enc_map(&mAl, d_alo, D0c, Nn, 128);
    enc_map(&mBh, B1h, D0c, D1, 256);
    enc_map(&mBl, B1l, D0c, D1, 256);
    cudaStreamWaitEvent(0, evB[0], 0);
    k_tma_gemm<<<dim3(D1 / 256, Nn / 128), GEMM_THREADS, GEMM_SMEM>>>(
        mAh, mAl, mBh, mBl, d_ahi, d_alo, B1h, B1l, d_xp, D0c, D1,
        as1, ad1, sv0, dv0, 0, C1c);

    // s2: remaining weight conversions + output zero (overlap with main chain)
    k_wconv_t<<<dim3(D2 / 32, D1 / 32), tb, 0, s2>>>(W2, D1, D2, B2h, B2l);
    cudaEventRecord(evB[1], s2);
    k_wconv_t<<<dim3(D3 / 32, D2 / 32), tb, 0, s2>>>(W3, D2, D3, B3h, B3l);
    cudaEventRecord(evB[2], s2);
    for (int k = 0; k < Kk; k++)
        k_wconv_t<<<dim3(NP / 32, D3 / 32), tb, 0, s2>>>(
            Wh + (size_t)k * D3 * Mm, D3, Mm,
            BHh + (size_t)k * NP * D3, BHl + (size_t)k * NP * D3);
    k_pad_as<<<(Kk * 512) / 256, 256, 0, s2>>>(ash, adh, d_asf, d_adf);
    cudaEventRecord(evB[3], s2);
    k_zero_f<<<2048, 256, 0, s2>>>(full, (size_t)Nn * Gg);
    cudaEventRecord(evB[4], s2);

    // main: agg1 (needs CSR), reads sv0
    cudaStreamWaitEvent(0, evCSR, 0);
    k_agg_post<<<Nn, 256>>>(d_xp, sv0, dv0, d_off, d_csr, b1, g1, be1,
                            d_ahi, d_alo, C1c);
    cudaEventRecord(evA1, 0);
    // s2: re-zero buf0 for layer-3 GEMM once agg1 has consumed it
    cudaStreamWaitEvent(s2, evA1, 0);
    k_zero_sd<<<(Nn * Hh) / 256, 256, 0, s2>>>(sv0, dv0, Nn * Hh);
    cudaEventRecord(evZ2, s2);

    // main: GEMM2 (-> sv1) + agg2
    enc_map(&mAh, d_ahi, D1, Nn, 128);
    enc_map(&mAl, d_alo, D1, Nn, 128);
    enc_map(&mBh, B2h, D1, D2, 256);
    enc_map(&mBl, B2l, D1, D2, 256);
    cudaStreamWaitEvent(0, evB[1], 0);
    k_tma_gemm<<<dim3(D2 / 256, Nn / 128), GEMM_THREADS, GEMM_SMEM>>>(
        mAh, mAl, mBh, mBl, d_ahi, d_alo, B2h, B2l, d_xp, D1, D2,
        as2, ad2, sv1, dv1, 0, C2c);
    k_agg_post<<<Nn, 256>>>(d_xp, sv1, dv1, d_off, d_csr, b2, g2, be2,
                            d_ahi, d_alo, C2c);
    cudaEventRecord(evA2, 0);
    // s2: re-zero buf1 for hydra GEMM once agg2 has consumed it
    cudaStreamWaitEvent(s2, evA2, 0);
    k_zero_sd<<<(Nn * Hh) / 256, 256, 0, s2>>>(sv1, dv1, Nn * Hh);
    cudaEventRecord(evZ3, s2);

    // main: GEMM3 (-> sv0) + agg3
    enc_map(&mAh, d_ahi, D2, Nn, 128);
    enc_map(&mAl, d_alo, D2, Nn, 128);
    enc_map(&mBh, B3h, D2, D3, 256);
    enc_map(&mBl, B3l, D2, D3, 256);
    cudaStreamWaitEvent(0, evB[2], 0);
    cudaStreamWaitEvent(0, evZ2, 0);
    k_tma_gemm<<<dim3(D3 / 256, Nn / 128), GEMM_THREADS, GEMM_SMEM>>>(
        mAh, mAl, mBh, mBl, d_ahi, d_alo, B3h, B3l, d_xp, D2, D3,
        as3, ad3, sv0, dv0, 0, C3c);
    k_agg_post<<<Nn, 256>>>(d_xp, sv0, dv0, d_off, d_csr, b3, g3, be3,
                            d_ahi, d_alo, C3c);

    // main: hydra GEMM (-> sv1) + fused hydra agg
    enc_map(&mAh, d_ahi, D3, Nn, 128);
    enc_map(&mAl, d_alo, D3, Nn, 128);
    enc_map(&mBh, BHh, D3, Kk * NP, 256);
    enc_map(&mBl, BHl, D3, Kk * NP, 256);
    cudaStreamWaitEvent(0, evB[3], 0);
    cudaStreamWaitEvent(0, evZ3, 0);
    k_tma_gemm<<<dim3((Kk * NP) / 256, Nn / 128), GEMM_THREADS, GEMM_SMEM>>>(
        mAh, mAl, mBh, mBl, d_ahi, d_alo, BHh, BHl, d_xp, D3, Kk * NP,
        d_asf, d_adf, sv1, dv1, 1, NP);

    cudaStreamWaitEvent(0, evB[4], 0);
    k_agg_hydra<<<Nn, 256>>>(d_xp, sv1, dv1, d_off, d_csr, bh, idx, full, pho);
}